// round 2
// baseline (speedup 1.0000x reference)
#include <cuda_runtime.h>

// Problem constants (fixed shapes per problem spec)
namespace {
constexpr int Bn  = 16;
constexpr int Nn  = 4096;
constexpr int Sn  = 1024;
constexpr int Kn  = 32;
constexpr int CPn = 64;   // point feature channels
constexpr int C3n = 128;  // final MLP out channels
}

// Scratch (static device arrays; no allocation)
__device__ int   g_knn[Bn * Sn * Kn];
__device__ float g_pn[Bn * Nn];
__device__ float g_ptsT[(size_t)Bn * Nn * CPn];  // points transposed to (B,N,CP)

// ---------------------------------------------------------------------------
// Kernel 1: farthest point sampling. One CTA per batch, 512 threads,
// xyz + running min-dist in registers (8 points/thread, strided layout).
// ---------------------------------------------------------------------------
__global__ __launch_bounds__(512) void fps_kernel(const float* __restrict__ xyz,
                                                  float* __restrict__ out_xyz)
{
    int b = blockIdx.x;
    int t = threadIdx.x;
    const float* xb = xyz + (size_t)b * Nn * 3;

    float px[8], py[8], pz[8], dist[8];
#pragma unroll
    for (int i = 0; i < 8; i++) {
        int j = t + i * 512;
        px[i] = xb[j * 3 + 0];
        py[i] = xb[j * 3 + 1];
        pz[i] = xb[j * 3 + 2];
        dist[i] = 1e10f;
    }

    __shared__ float s_val[16];
    __shared__ int   s_idx[16];
    __shared__ float s_cx, s_cy, s_cz;
    __shared__ int   s_far;

    if (t == 0) {
        s_cx = xb[0]; s_cy = xb[1]; s_cz = xb[2];
        out_xyz[(size_t)(b * Sn) * 3 + 0] = xb[0];
        out_xyz[(size_t)(b * Sn) * 3 + 1] = xb[1];
        out_xyz[(size_t)(b * Sn) * 3 + 2] = xb[2];
    }
    __syncthreads();

    int lane = t & 31, wid = t >> 5;

    for (int it = 1; it < Sn; ++it) {
        float cx = s_cx, cy = s_cy, cz = s_cz;
        float mv = -1.0f; int mi = 0;
#pragma unroll
        for (int i = 0; i < 8; i++) {
            float dx = px[i] - cx, dy = py[i] - cy, dz = pz[i] - cz;
            float d  = fmaf(dz, dz, fmaf(dy, dy, dx * dx));
            float nd = fminf(dist[i], d);
            dist[i] = nd;
            if (nd > mv) { mv = nd; mi = t + i * 512; }  // strict > keeps lowest index
        }
        // warp argmax reduce, lowest-index tiebreak (matches jnp.argmax)
#pragma unroll
        for (int off = 16; off; off >>= 1) {
            float ov = __shfl_down_sync(0xffffffffu, mv, off);
            int   oi = __shfl_down_sync(0xffffffffu, mi, off);
            if (ov > mv || (ov == mv && oi < mi)) { mv = ov; mi = oi; }
        }
        if (lane == 0) { s_val[wid] = mv; s_idx[wid] = mi; }
        __syncthreads();
        if (t < 32) {
            float v  = (t < 16) ? s_val[t] : -2.0f;
            int   ix = (t < 16) ? s_idx[t] : 0;
#pragma unroll
            for (int off = 8; off; off >>= 1) {
                float ov = __shfl_down_sync(0xffffffffu, v, off);
                int   oi = __shfl_down_sync(0xffffffffu, ix, off);
                if (ov > v || (ov == v && oi < ix)) { v = ov; ix = oi; }
            }
            if (t == 0) s_far = ix;
        }
        __syncthreads();
        int far = s_far;
        if ((far & 511) == t) {
            int sl = far >> 9;
            s_cx = px[sl]; s_cy = py[sl]; s_cz = pz[sl];
            out_xyz[(size_t)(b * Sn + it) * 3 + 0] = px[sl];
            out_xyz[(size_t)(b * Sn + it) * 3 + 1] = py[sl];
            out_xyz[(size_t)(b * Sn + it) * 3 + 2] = pz[sl];
        }
        __syncthreads();
    }
}

// ---------------------------------------------------------------------------
// Kernel 2: per-point squared norms (for the reference kNN distance formula)
// ---------------------------------------------------------------------------
__global__ void pn_kernel(const float* __restrict__ xyz)
{
    int i = blockIdx.x * 256 + threadIdx.x;
    if (i < Bn * Nn) {
        float x = xyz[i * 3 + 0], y = xyz[i * 3 + 1], z = xyz[i * 3 + 2];
        g_pn[i] = fmaf(z, z, fmaf(y, y, x * x));
    }
}

// ---------------------------------------------------------------------------
// Kernel 3: transpose points (B,CP,N) -> (B,N,CP) so gathers are contiguous.
// ---------------------------------------------------------------------------
__global__ void transpose_kernel(const float* __restrict__ pts)
{
    __shared__ float tile[32][33];
    int b  = blockIdx.z;
    int n0 = blockIdx.x * 32;
    int c0 = blockIdx.y * 32;
    int tx = threadIdx.x, ty = threadIdx.y;
    const float* src = pts + (size_t)b * CPn * Nn;
#pragma unroll
    for (int i = 0; i < 32; i += 8)
        tile[ty + i][tx] = src[(size_t)(c0 + ty + i) * Nn + n0 + tx];
    __syncthreads();
    float* dst = g_ptsT + (size_t)b * Nn * CPn;
#pragma unroll
    for (int i = 0; i < 32; i += 8)
        dst[(size_t)(n0 + ty + i) * CPn + c0 + tx] = tile[tx][ty + i];
}

// ---------------------------------------------------------------------------
// Kernel 4: kNN. Thread-per-centroid; xyz + |p|^2 tiles in SMEM (broadcast
// reads); register-resident sorted top-32 with branchless unrolled insert.
// Selection key = (d2, index) ascending, matching lax.top_k tie behavior.
// ---------------------------------------------------------------------------
__global__ __launch_bounds__(128) void knn_kernel(const float* __restrict__ xyz,
                                                  const float* __restrict__ new_xyz)
{
    extern __shared__ float sm_knn[];
    float* sx  = sm_knn;
    float* sy  = sm_knn + Nn;
    float* sz  = sm_knn + 2 * Nn;
    float* spn = sm_knn + 3 * Nn;

    int b = blockIdx.y;
    const float* xb = xyz + (size_t)b * Nn * 3;
    for (int j = threadIdx.x; j < Nn; j += 128) {
        sx[j] = xb[j * 3 + 0];
        sy[j] = xb[j * 3 + 1];
        sz[j] = xb[j * 3 + 2];
        spn[j] = g_pn[b * Nn + j];
    }
    __syncthreads();

    int s = blockIdx.x * 128 + threadIdx.x;
    const float* cp = new_xyz + ((size_t)b * Sn + s) * 3;
    float nx = cp[0], ny = cp[1], nz = cp[2];
    float cn = fmaf(nz, nz, fmaf(ny, ny, nx * nx));

    float bd[Kn]; int bi[Kn];   // sorted descending: bd[0] = current worst
#pragma unroll
    for (int t = 0; t < Kn; t++) { bd[t] = 3.0e38f; bi[t] = -1; }

    for (int j = 0; j < Nn; j++) {
        float dot = fmaf(nz, sz[j], fmaf(ny, sy[j], nx * sx[j]));
        float d = (cn + spn[j]) - 2.0f * dot;
        if (d < bd[0]) {
            // branchless sorted insert (evicts largest); stays in registers
#pragma unroll
            for (int t = 0; t < Kn; t++) {
                float nv = (t < Kn - 1) ? bd[t + 1] : -3.0e38f;
                int   ni = (t < Kn - 1) ? bi[t + 1] : 0;
                bool c1 = nv > d;
                bool c2 = bd[t] > d;
                bd[t] = c1 ? nv : (c2 ? d : bd[t]);
                bi[t] = c1 ? ni : (c2 ? j : bi[t]);
            }
        }
    }
    int base = (b * Sn + s) * Kn;
#pragma unroll
    for (int t = 0; t < Kn; t++) g_knn[base + t] = bi[t];
}

// ---------------------------------------------------------------------------
// Kernel 5: fused gather + 3-layer MLP + maxpool. 8 centroids (256 points)
// per 256-thread block. Weights + activations in SMEM, 4pt x 16ch register
// tiles, float4 activation loads + broadcast float4 weight loads.
// SMEM float layout (stride 260 for activations: bank-friendly, 16B aligned):
//   W1t[67][64] W2t[64][64] W3t[64][128] b1[64] b2[64] b3[128]
//   Xt[67][260]  H1[64][260]   (H2 aliases Xt)
// ---------------------------------------------------------------------------
constexpr int ST       = 260;
constexpr int OFF_W1T  = 0;
constexpr int OFF_W2T  = OFF_W1T + 67 * 64;      // 4288
constexpr int OFF_W3T  = OFF_W2T + 64 * 64;      // 8384
constexpr int OFF_B1   = OFF_W3T + 64 * 128;     // 16576
constexpr int OFF_B2   = OFF_B1 + 64;            // 16640
constexpr int OFF_B3   = OFF_B2 + 64;            // 16704
constexpr int OFF_XT   = OFF_B3 + 128;           // 16832
constexpr int OFF_H1   = OFF_XT + 67 * ST;       // 34252
constexpr int SMEM_FLOATS = OFF_H1 + 64 * ST;    // 50892
constexpr int MLP_SMEM_BYTES = SMEM_FLOATS * 4;  // 203568

__global__ __launch_bounds__(256) void mlp_kernel(
    const float* __restrict__ xyz,
    const float* __restrict__ W1, const float* __restrict__ b1,
    const float* __restrict__ W2, const float* __restrict__ b2,
    const float* __restrict__ W3, const float* __restrict__ b3,
    float* __restrict__ out_np)
{
    extern __shared__ float sm[];
    float* sW1t = sm + OFF_W1T;
    float* sW2t = sm + OFF_W2T;
    float* sW3t = sm + OFF_W3T;
    float* sB1  = sm + OFF_B1;
    float* sB2  = sm + OFF_B2;
    float* sB3  = sm + OFF_B3;
    float* sXt  = sm + OFF_XT;
    float* sH1  = sm + OFF_H1;
    float* sH2  = sXt;  // alias: X dead after layer 1

    int tid = threadIdx.x;
    int b   = blockIdx.y;
    int s0  = blockIdx.x * 8;

    // load weights transposed: sWt[c][o] = W[o][c]
    for (int i = tid; i < 64 * 67; i += 256) { int o = i / 67, c = i % 67; sW1t[c * 64 + o] = W1[i]; }
    for (int i = tid; i < 64 * 64; i += 256) { int o = i >> 6, c = i & 63; sW2t[c * 64 + o] = W2[i]; }
    for (int i = tid; i < 128 * 64; i += 256){ int o = i >> 6, c = i & 63; sW3t[c * 128 + o] = W3[i]; }
    if (tid < 64)  sB1[tid] = b1[tid];
    if (tid < 64)  sB2[tid] = b2[tid];
    if (tid < 128) sB3[tid] = b3[tid];

    // gather: Xt[c][p], channels 0..2 = neighbor xyz, 3..66 = point features
    {
        int wid = tid >> 5, lane = tid & 31;
        for (int p = wid; p < 256; p += 8) {
            int s = s0 + (p >> 5);
            int j = g_knn[((b * Sn + s) << 5) + (p & 31)];
            const float* pr = g_ptsT + ((size_t)(b * Nn + j)) * CPn;
            float v0 = (lane < 3) ? xyz[((size_t)(b * Nn + j)) * 3 + lane] : pr[lane - 3];
            sXt[lane * ST + p]        = v0;
            sXt[(lane + 32) * ST + p] = pr[lane + 29];
            if (lane < 3) sXt[(lane + 64) * ST + p] = pr[lane + 61];
        }
    }
    __syncthreads();

    int tx = tid & 63, ty = tid >> 6;
    int p0 = tx * 4;

    // ---------------- layer 1: 67 -> 64 ----------------
    {
        int o0 = ty * 16;
        float acc[4][16];
#pragma unroll
        for (int i = 0; i < 4; i++)
#pragma unroll
            for (int o = 0; o < 16; o++) acc[i][o] = 0.0f;

        for (int c = 0; c < 67; c++) {
            float4 xv = *(const float4*)(sXt + c * ST + p0);
            const float4* wp = (const float4*)(sW1t + c * 64 + o0);
            float4 w0 = wp[0], w1 = wp[1], w2 = wp[2], w3 = wp[3];
            float xs[4] = {xv.x, xv.y, xv.z, xv.w};
            float ws[16] = {w0.x, w0.y, w0.z, w0.w, w1.x, w1.y, w1.z, w1.w,
                            w2.x, w2.y, w2.z, w2.w, w3.x, w3.y, w3.z, w3.w};
#pragma unroll
            for (int i = 0; i < 4; i++) {
                float xi = xs[i];
#pragma unroll
                for (int o = 0; o < 16; o++) acc[i][o] = fmaf(xi, ws[o], acc[i][o]);
            }
        }
#pragma unroll
        for (int o = 0; o < 16; o++) {
            float bia = sB1[o0 + o];
            float4 v;
            v.x = fmaxf(acc[0][o] + bia, 0.0f);
            v.y = fmaxf(acc[1][o] + bia, 0.0f);
            v.z = fmaxf(acc[2][o] + bia, 0.0f);
            v.w = fmaxf(acc[3][o] + bia, 0.0f);
            *(float4*)(sH1 + (o0 + o) * ST + p0) = v;
        }
    }
    __syncthreads();

    // ---------------- layer 2: 64 -> 64 ----------------
    {
        int o0 = ty * 16;
        float acc[4][16];
#pragma unroll
        for (int i = 0; i < 4; i++)
#pragma unroll
            for (int o = 0; o < 16; o++) acc[i][o] = 0.0f;

        for (int c = 0; c < 64; c++) {
            float4 xv = *(const float4*)(sH1 + c * ST + p0);
            const float4* wp = (const float4*)(sW2t + c * 64 + o0);
            float4 w0 = wp[0], w1 = wp[1], w2 = wp[2], w3 = wp[3];
            float xs[4] = {xv.x, xv.y, xv.z, xv.w};
            float ws[16] = {w0.x, w0.y, w0.z, w0.w, w1.x, w1.y, w1.z, w1.w,
                            w2.x, w2.y, w2.z, w2.w, w3.x, w3.y, w3.z, w3.w};
#pragma unroll
            for (int i = 0; i < 4; i++) {
                float xi = xs[i];
#pragma unroll
                for (int o = 0; o < 16; o++) acc[i][o] = fmaf(xi, ws[o], acc[i][o]);
            }
        }
#pragma unroll
        for (int o = 0; o < 16; o++) {
            float bia = sB2[o0 + o];
            float4 v;
            v.x = fmaxf(acc[0][o] + bia, 0.0f);
            v.y = fmaxf(acc[1][o] + bia, 0.0f);
            v.z = fmaxf(acc[2][o] + bia, 0.0f);
            v.w = fmaxf(acc[3][o] + bia, 0.0f);
            *(float4*)(sH2 + (o0 + o) * ST + p0) = v;
        }
    }
    __syncthreads();

    // ---------------- layer 3: 64 -> 128 + maxpool over k ----------------
    {
        int q  = tx & 7;        // 8 threads per centroid (4 points each)
        int sl = tx >> 3;       // local centroid 0..7
        for (int pass = 0; pass < 2; pass++) {
            int o0 = ty * 16 + pass * 64;
            float acc[4][16];
#pragma unroll
            for (int i = 0; i < 4; i++)
#pragma unroll
                for (int o = 0; o < 16; o++) acc[i][o] = 0.0f;

            for (int c = 0; c < 64; c++) {
                float4 xv = *(const float4*)(sH2 + c * ST + p0);
                const float4* wp = (const float4*)(sW3t + c * 128 + o0);
                float4 w0 = wp[0], w1 = wp[1], w2 = wp[2], w3 = wp[3];
                float xs[4] = {xv.x, xv.y, xv.z, xv.w};
                float ws[16] = {w0.x, w0.y, w0.z, w0.w, w1.x, w1.y, w1.z, w1.w,
                                w2.x, w2.y, w2.z, w2.w, w3.x, w3.y, w3.z, w3.w};
#pragma unroll
                for (int i = 0; i < 4; i++) {
                    float xi = xs[i];
#pragma unroll
                    for (int o = 0; o < 16; o++) acc[i][o] = fmaf(xi, ws[o], acc[i][o]);
                }
            }
#pragma unroll
            for (int o = 0; o < 16; o++) {
                float bia = sB3[o0 + o];
                // relu(v+b) maxpool: bias/relu monotone -> max first, then bias+relu
                float m = fmaxf(fmaxf(acc[0][o], acc[1][o]), fmaxf(acc[2][o], acc[3][o]));
                m = fmaxf(m + bia, 0.0f);
                m = fmaxf(m, __shfl_xor_sync(0xffffffffu, m, 1));
                m = fmaxf(m, __shfl_xor_sync(0xffffffffu, m, 2));
                m = fmaxf(m, __shfl_xor_sync(0xffffffffu, m, 4));
                if (q == 0)
                    out_np[((size_t)b * C3n + (o0 + o)) * Sn + (s0 + sl)] = m;
            }
        }
    }
}

// ---------------------------------------------------------------------------
extern "C" void kernel_launch(void* const* d_in, const int* in_sizes, int n_in,
                              void* d_out, int out_size)
{
    (void)in_sizes; (void)n_in; (void)out_size;
    const float* xyz = (const float*)d_in[0];
    const float* pts = (const float*)d_in[1];
    const float* W1  = (const float*)d_in[2];
    const float* b1  = (const float*)d_in[3];
    const float* W2  = (const float*)d_in[4];
    const float* b2  = (const float*)d_in[5];
    const float* W3  = (const float*)d_in[6];
    const float* b3  = (const float*)d_in[7];

    float* out      = (float*)d_out;
    float* out_xyz  = out;                       // (B,S,3)
    float* out_np   = out + (size_t)Bn * Sn * 3; // (B,128,S)

    cudaFuncSetAttribute(knn_kernel, cudaFuncAttributeMaxDynamicSharedMemorySize, 4 * Nn * 4);
    cudaFuncSetAttribute(mlp_kernel, cudaFuncAttributeMaxDynamicSharedMemorySize, MLP_SMEM_BYTES);

    // prep first (independent of FPS), then the sequential chain
    pn_kernel<<<(Bn * Nn + 255) / 256, 256>>>(xyz);
    transpose_kernel<<<dim3(Nn / 32, CPn / 32, Bn), dim3(32, 8)>>>(pts);
    fps_kernel<<<Bn, 512>>>(xyz, out_xyz);
    knn_kernel<<<dim3(Sn / 128, Bn), 128, 4 * Nn * 4>>>(xyz, out_xyz);
    mlp_kernel<<<dim3(Sn / 8, Bn), 256, MLP_SMEM_BYTES>>>(xyz, W1, b1, W2, b2, W3, b3, out_np);
}

// round 3
// speedup vs baseline: 1.4127x; 1.4127x over previous
#include <cuda_runtime.h>

// Problem constants (fixed shapes per problem spec)
namespace {
constexpr int Bn  = 16;
constexpr int Nn  = 4096;
constexpr int Sn  = 1024;
constexpr int Kn  = 32;
constexpr int CPn = 64;   // point feature channels
constexpr int C3n = 128;  // final MLP out channels
}

// Scratch (static device arrays; no allocation)
__device__ int   g_knn[Bn * Sn * Kn];
__device__ float g_ptsT[(size_t)Bn * Nn * CPn];  // points transposed to (B,N,CP)

// ---------------------------------------------------------------------------
// f32x2 packed-math helpers (FFMA2: 2 fp32 FMAs per instruction)
// ---------------------------------------------------------------------------
__device__ __forceinline__ unsigned long long pk2(float lo, float hi) {
    unsigned long long r;
    asm("mov.b64 %0, {%1, %2};" : "=l"(r) : "f"(lo), "f"(hi));
    return r;
}
__device__ __forceinline__ void fma2(unsigned long long& d,
                                     unsigned long long a, unsigned long long b) {
    asm("fma.rn.f32x2 %0, %1, %2, %0;" : "+l"(d) : "l"(a), "l"(b));
}
__device__ __forceinline__ float2 up2(unsigned long long v) {
    float lo, hi;
    asm("mov.b64 {%0, %1}, %2;" : "=f"(lo), "=f"(hi) : "l"(v));
    return make_float2(lo, hi);
}

// ---------------------------------------------------------------------------
// Kernel 1: FPS (blocks 0..15, one per batch) + points-transpose (blocks 16..143)
// FPS: 512 threads, 8 pts/thread in regs, xyz mirrored in SMEM so the final
// argmax reduce is done redundantly by every thread -> ONE barrier per iter.
// Winner key packs (fp32 bits of dist << 32) | ~idx : max-reduce == argmax
// with lowest-index tiebreak (matches jnp.argmax).
// ---------------------------------------------------------------------------
constexpr int FPS_SMEM_BYTES = 3 * Nn * 4 + 2 * 16 * 8 + 64;

__global__ __launch_bounds__(512) void fps_prep_kernel(const float* __restrict__ xyz,
                                                       const float* __restrict__ pts,
                                                       float* __restrict__ out_xyz)
{
    extern __shared__ float dsm[];
    int t = threadIdx.x;

    if (blockIdx.x >= 16) {
        // ---- transpose blocks: (B,CP,N) -> (B,N,CP), 512-wide n-chunks ----
        float (*tile)[33] = (float (*)[33])dsm;
        int bx = blockIdx.x - 16;
        int b  = bx >> 3;
        int n0 = (bx & 7) * 512;
        int txx = t & 31, tyy = t >> 5;   // tyy 0..15
        const float* src = pts + (size_t)b * CPn * Nn;
        float* dst = g_ptsT + (size_t)b * Nn * CPn;
        for (int ct = 0; ct < 2; ct++) {
            int c0 = ct * 32;
            for (int nt = 0; nt < 16; nt++) {
                int nn0 = n0 + nt * 32;
                tile[tyy][txx]      = src[(size_t)(c0 + tyy) * Nn + nn0 + txx];
                tile[tyy + 16][txx] = src[(size_t)(c0 + tyy + 16) * Nn + nn0 + txx];
                __syncthreads();
                dst[(size_t)(nn0 + tyy) * CPn + c0 + txx]      = tile[txx][tyy];
                dst[(size_t)(nn0 + tyy + 16) * CPn + c0 + txx] = tile[txx][tyy + 16];
                __syncthreads();
            }
        }
        return;
    }

    // ---- FPS blocks ----
    float* sx = dsm;
    float* sy = dsm + Nn;
    float* sz = dsm + 2 * Nn;
    unsigned long long* skey = (unsigned long long*)(dsm + 3 * Nn);

    int b = blockIdx.x;
    const float* xb = xyz + (size_t)b * Nn * 3;

    float px[8], py[8], pz[8], dist[8];
#pragma unroll
    for (int i = 0; i < 8; i++) {
        int j = t + i * 512;
        float x = xb[3 * j], y = xb[3 * j + 1], z = xb[3 * j + 2];
        px[i] = x; py[i] = y; pz[i] = z;
        sx[j] = x; sy[j] = y; sz[j] = z;
        dist[i] = 1e10f;
    }
    __syncthreads();

    float cx = sx[0], cy = sy[0], cz = sz[0];
    if (t == 0) {
        float* o = out_xyz + (size_t)b * Sn * 3;
        o[0] = cx; o[1] = cy; o[2] = cz;
    }

    int lane = t & 31, wid = t >> 5;

    for (int it = 1; it < Sn; ++it) {
        float mv = 0.0f; int mi = 0x7fffffff;
#pragma unroll
        for (int i = 0; i < 8; i++) {
            float dx = px[i] - cx, dy = py[i] - cy, dz = pz[i] - cz;
            float d  = fmaf(dz, dz, fmaf(dy, dy, dx * dx));
            float nd = fminf(dist[i], d);
            dist[i] = nd;
            if (nd > mv) { mv = nd; mi = t + i * 512; }  // strict > -> lowest idx
        }
        unsigned long long key =
            ((unsigned long long)__float_as_uint(mv) << 32) | (unsigned)(~mi);
#pragma unroll
        for (int off = 16; off; off >>= 1) {
            unsigned long long ok = __shfl_down_sync(0xffffffffu, key, off);
            if (ok > key) key = ok;
        }
        if (lane == 0) skey[(it & 1) * 16 + wid] = key;
        __syncthreads();
        unsigned long long k = skey[(it & 1) * 16];
#pragma unroll
        for (int w = 1; w < 16; w++) {
            unsigned long long o = skey[(it & 1) * 16 + w];
            if (o > k) k = o;
        }
        int far = ~(unsigned)k;
        cx = sx[far]; cy = sy[far]; cz = sz[far];
        if (t == 0) {
            float* o = out_xyz + ((size_t)b * Sn + it) * 3;
            o[0] = cx; o[1] = cy; o[2] = cz;
        }
    }
}

// ---------------------------------------------------------------------------
// Kernel 2: kNN — warp per centroid, warp-collective sorted top-32.
// Lane l holds the l-th smallest (d, idx) key. 32 candidate distances are
// computed per batch (one per lane from the float4 SMEM tile); qualifying
// candidates are inserted one at a time: position via ballot+popc, shift via
// one shfl_up. Exact (d, idx)-lexicographic selection (ties -> lower index).
// ---------------------------------------------------------------------------
__global__ __launch_bounds__(256) void knn_kernel(const float* __restrict__ xyz,
                                                  const float* __restrict__ new_xyz)
{
    extern __shared__ float4 sp[];   // 4096 x (x,y,z,|p|^2) = 64KB
    int b = blockIdx.y;
    const float* xb = xyz + (size_t)b * Nn * 3;
    for (int j = threadIdx.x; j < Nn; j += 256) {
        float x = xb[3 * j], y = xb[3 * j + 1], z = xb[3 * j + 2];
        sp[j] = make_float4(x, y, z, fmaf(z, z, fmaf(y, y, x * x)));
    }
    __syncthreads();

    const unsigned FULL = 0xffffffffu;
    int warp = threadIdx.x >> 5, lane = threadIdx.x & 31;
    const float INF = __int_as_float(0x7f800000);

    for (int cc = 0; cc < 8; cc++) {
        int s = blockIdx.x * 64 + cc * 8 + warp;
        const float* cp = new_xyz + ((size_t)b * Sn + s) * 3;
        float nx = cp[0], ny = cp[1], nz = cp[2];
        float cn = fmaf(nz, nz, fmaf(ny, ny, nx * nx));

        float cur_d = INF; int cur_i = 0x7fffffff;
        float wmax = INF;

        for (int j0 = 0; j0 < Nn; j0 += 32) {
            float4 p = sp[j0 + lane];
            float dot = fmaf(nz, p.z, fmaf(ny, p.y, nx * p.x));
            float d = (cn + p.w) - 2.0f * dot;
            unsigned mask = __ballot_sync(FULL, d <= wmax);
            while (mask) {
                int src = __ffs(mask) - 1;
                mask &= mask - 1;
                float dn = __shfl_sync(FULL, d, src);
                int   ix = j0 + src;
                bool less = (cur_d < dn) || (cur_d == dn && cur_i < ix);
                int pos = __popc(__ballot_sync(FULL, less));
                if (pos < 32) {
                    float ud = __shfl_up_sync(FULL, cur_d, 1);
                    int   ui = __shfl_up_sync(FULL, cur_i, 1);
                    if (lane > pos)       { cur_d = ud; cur_i = ui; }
                    else if (lane == pos) { cur_d = dn; cur_i = ix; }
                    wmax = __shfl_sync(FULL, cur_d, 31);
                }
            }
        }
        g_knn[((b * Sn + s) << 5) + lane] = cur_i;
        cur_d = INF; cur_i = 0x7fffffff; wmax = INF;  // (reset handled above)
    }
}

// ---------------------------------------------------------------------------
// Kernel 3: fused gather + 3-layer MLP + maxpool, now with packed FFMA2.
// 8 centroids (256 points) per 256-thread block; weights + activations SMEM.
// ---------------------------------------------------------------------------
constexpr int ST       = 260;
constexpr int OFF_W1T  = 0;
constexpr int OFF_W2T  = OFF_W1T + 67 * 64;      // 4288
constexpr int OFF_W3T  = OFF_W2T + 64 * 64;      // 8384
constexpr int OFF_B1   = OFF_W3T + 64 * 128;     // 16576
constexpr int OFF_B2   = OFF_B1 + 64;
constexpr int OFF_B3   = OFF_B2 + 64;
constexpr int OFF_XT   = OFF_B3 + 128;           // 16832
constexpr int OFF_H1   = OFF_XT + 67 * ST;       // 34252
constexpr int SMEM_FLOATS = OFF_H1 + 64 * ST;    // 50892
constexpr int MLP_SMEM_BYTES = SMEM_FLOATS * 4;  // 203568

// One dense layer tile: 4 points x 16 outs per thread, outputs in f32x2 pairs.
template <int C, int WS>
__device__ __forceinline__ void layer_f32x2(const float* __restrict__ Xs,
                                            const float* __restrict__ Wt,
                                            const float* __restrict__ Bs,
                                            float* __restrict__ Hs,
                                            int p0, int o0)
{
    unsigned long long acc[4][8];
#pragma unroll
    for (int i = 0; i < 4; i++)
#pragma unroll
        for (int o = 0; o < 8; o++) acc[i][o] = pk2(0.0f, 0.0f);

    for (int c = 0; c < C; c++) {
        float4 xv = *(const float4*)(Xs + c * ST + p0);
        const float4* wp = (const float4*)(Wt + c * WS + o0);
        float4 w0 = wp[0], w1 = wp[1], w2 = wp[2], w3 = wp[3];
        unsigned long long xq[4] = {pk2(xv.x, xv.x), pk2(xv.y, xv.y),
                                    pk2(xv.z, xv.z), pk2(xv.w, xv.w)};
        unsigned long long wq[8] = {pk2(w0.x, w0.y), pk2(w0.z, w0.w),
                                    pk2(w1.x, w1.y), pk2(w1.z, w1.w),
                                    pk2(w2.x, w2.y), pk2(w2.z, w2.w),
                                    pk2(w3.x, w3.y), pk2(w3.z, w3.w)};
#pragma unroll
        for (int i = 0; i < 4; i++)
#pragma unroll
            for (int o = 0; o < 8; o++) fma2(acc[i][o], xq[i], wq[o]);
    }
#pragma unroll
    for (int o = 0; o < 8; o++) {
        float b0 = Bs[o0 + 2 * o], b1 = Bs[o0 + 2 * o + 1];
        float2 a0 = up2(acc[0][o]), a1 = up2(acc[1][o]);
        float2 a2 = up2(acc[2][o]), a3 = up2(acc[3][o]);
        float4 ve = make_float4(fmaxf(a0.x + b0, 0.f), fmaxf(a1.x + b0, 0.f),
                                fmaxf(a2.x + b0, 0.f), fmaxf(a3.x + b0, 0.f));
        float4 vo = make_float4(fmaxf(a0.y + b1, 0.f), fmaxf(a1.y + b1, 0.f),
                                fmaxf(a2.y + b1, 0.f), fmaxf(a3.y + b1, 0.f));
        *(float4*)(Hs + (o0 + 2 * o) * ST + p0)     = ve;
        *(float4*)(Hs + (o0 + 2 * o + 1) * ST + p0) = vo;
    }
}

__global__ __launch_bounds__(256) void mlp_kernel(
    const float* __restrict__ xyz,
    const float* __restrict__ W1, const float* __restrict__ b1,
    const float* __restrict__ W2, const float* __restrict__ b2,
    const float* __restrict__ W3, const float* __restrict__ b3,
    float* __restrict__ out_np)
{
    extern __shared__ float sm[];
    float* sW1t = sm + OFF_W1T;
    float* sW2t = sm + OFF_W2T;
    float* sW3t = sm + OFF_W3T;
    float* sB1  = sm + OFF_B1;
    float* sB2  = sm + OFF_B2;
    float* sB3  = sm + OFF_B3;
    float* sXt  = sm + OFF_XT;
    float* sH1  = sm + OFF_H1;
    float* sH2  = sXt;  // alias: X dead after layer 1

    int tid = threadIdx.x;
    int b   = blockIdx.y;
    int s0  = blockIdx.x * 8;

    for (int i = tid; i < 64 * 67; i += 256) { int o = i / 67, c = i % 67; sW1t[c * 64 + o] = W1[i]; }
    for (int i = tid; i < 64 * 64; i += 256) { int o = i >> 6, c = i & 63; sW2t[c * 64 + o] = W2[i]; }
    for (int i = tid; i < 128 * 64; i += 256){ int o = i >> 6, c = i & 63; sW3t[c * 128 + o] = W3[i]; }
    if (tid < 64)  sB1[tid] = b1[tid];
    if (tid < 64)  sB2[tid] = b2[tid];
    if (tid < 128) sB3[tid] = b3[tid];

    // gather: Xt[c][p], channels 0..2 = neighbor xyz, 3..66 = point features
    {
        int wid = tid >> 5, lane = tid & 31;
        for (int p = wid; p < 256; p += 8) {
            int s = s0 + (p >> 5);
            int j = g_knn[((b * Sn + s) << 5) + (p & 31)];
            const float* pr = g_ptsT + ((size_t)(b * Nn + j)) * CPn;
            float v0 = (lane < 3) ? xyz[((size_t)(b * Nn + j)) * 3 + lane] : pr[lane - 3];
            sXt[lane * ST + p]        = v0;
            sXt[(lane + 32) * ST + p] = pr[lane + 29];
            if (lane < 3) sXt[(lane + 64) * ST + p] = pr[lane + 61];
        }
    }
    __syncthreads();

    int tx = tid & 63, ty = tid >> 6;
    int p0 = tx * 4;

    layer_f32x2<67, 64>(sXt, sW1t, sB1, sH1, p0, ty * 16);
    __syncthreads();
    layer_f32x2<64, 64>(sH1, sW2t, sB2, sH2, p0, ty * 16);
    __syncthreads();

    // layer 3: 64 -> 128 + maxpool over k (bias/relu monotone: max first)
    {
        int q  = tx & 7;        // 8 threads per centroid (4 points each)
        int sl = tx >> 3;       // local centroid 0..7
        for (int pass = 0; pass < 2; pass++) {
            int o0 = ty * 16 + pass * 64;
            unsigned long long acc[4][8];
#pragma unroll
            for (int i = 0; i < 4; i++)
#pragma unroll
                for (int o = 0; o < 8; o++) acc[i][o] = pk2(0.0f, 0.0f);

            for (int c = 0; c < 64; c++) {
                float4 xv = *(const float4*)(sH2 + c * ST + p0);
                const float4* wp = (const float4*)(sW3t + c * 128 + o0);
                float4 w0 = wp[0], w1 = wp[1], w2 = wp[2], w3 = wp[3];
                unsigned long long xq[4] = {pk2(xv.x, xv.x), pk2(xv.y, xv.y),
                                            pk2(xv.z, xv.z), pk2(xv.w, xv.w)};
                unsigned long long wq[8] = {pk2(w0.x, w0.y), pk2(w0.z, w0.w),
                                            pk2(w1.x, w1.y), pk2(w1.z, w1.w),
                                            pk2(w2.x, w2.y), pk2(w2.z, w2.w),
                                            pk2(w3.x, w3.y), pk2(w3.z, w3.w)};
#pragma unroll
                for (int i = 0; i < 4; i++)
#pragma unroll
                    for (int o = 0; o < 8; o++) fma2(acc[i][o], xq[i], wq[o]);
            }
#pragma unroll
            for (int o = 0; o < 8; o++) {
                float b0 = sB3[o0 + 2 * o], b1v = sB3[o0 + 2 * o + 1];
                float2 a0 = up2(acc[0][o]), a1 = up2(acc[1][o]);
                float2 a2 = up2(acc[2][o]), a3 = up2(acc[3][o]);
                float me = fmaxf(fmaxf(a0.x, a1.x), fmaxf(a2.x, a3.x));
                float mo = fmaxf(fmaxf(a0.y, a1.y), fmaxf(a2.y, a3.y));
                me = fmaxf(me + b0, 0.0f);
                mo = fmaxf(mo + b1v, 0.0f);
#pragma unroll
                for (int off = 1; off < 8; off <<= 1) {
                    me = fmaxf(me, __shfl_xor_sync(0xffffffffu, me, off));
                    mo = fmaxf(mo, __shfl_xor_sync(0xffffffffu, mo, off));
                }
                if (q == 0) {
                    out_np[((size_t)b * C3n + (o0 + 2 * o)) * Sn + (s0 + sl)]     = me;
                    out_np[((size_t)b * C3n + (o0 + 2 * o + 1)) * Sn + (s0 + sl)] = mo;
                }
            }
        }
    }
}

// ---------------------------------------------------------------------------
extern "C" void kernel_launch(void* const* d_in, const int* in_sizes, int n_in,
                              void* d_out, int out_size)
{
    (void)in_sizes; (void)n_in; (void)out_size;
    const float* xyz = (const float*)d_in[0];
    const float* pts = (const float*)d_in[1];
    const float* W1  = (const float*)d_in[2];
    const float* b1  = (const float*)d_in[3];
    const float* W2  = (const float*)d_in[4];
    const float* b2  = (const float*)d_in[5];
    const float* W3  = (const float*)d_in[6];
    const float* b3  = (const float*)d_in[7];

    float* out      = (float*)d_out;
    float* out_xyz  = out;                       // (B,S,3)
    float* out_np   = out + (size_t)Bn * Sn * 3; // (B,128,S)

    cudaFuncSetAttribute(fps_prep_kernel, cudaFuncAttributeMaxDynamicSharedMemorySize, FPS_SMEM_BYTES);
    cudaFuncSetAttribute(knn_kernel, cudaFuncAttributeMaxDynamicSharedMemorySize, Nn * 16);
    cudaFuncSetAttribute(mlp_kernel, cudaFuncAttributeMaxDynamicSharedMemorySize, MLP_SMEM_BYTES);

    fps_prep_kernel<<<16 + 128, 512, FPS_SMEM_BYTES>>>(xyz, pts, out_xyz);
    knn_kernel<<<dim3(Sn / 64, Bn), 256, Nn * 16>>>(xyz, out_xyz);
    mlp_kernel<<<dim3(Sn / 8, Bn), 256, MLP_SMEM_BYTES>>>(xyz, W1, b1, W2, b2, W3, b3, out_np);
}

// round 4
// speedup vs baseline: 1.6015x; 1.1337x over previous
#include <cuda_runtime.h>

// Problem constants (fixed shapes per problem spec)
namespace {
constexpr int Bn  = 16;
constexpr int Nn  = 4096;
constexpr int Sn  = 1024;
constexpr int Kn  = 32;
constexpr int CPn = 64;   // point feature channels
constexpr int C3n = 128;  // final MLP out channels
}

// Scratch (static device arrays; no allocation)
__device__ int   g_knn[Bn * Sn * Kn];
__device__ float g_ptsT[(size_t)Bn * Nn * CPn];  // points transposed to (B,N,CP)

// ---------------------------------------------------------------------------
// f32x2 packed-math helpers
// ---------------------------------------------------------------------------
__device__ __forceinline__ unsigned long long pk2(float lo, float hi) {
    unsigned long long r;
    asm("mov.b64 %0, {%1, %2};" : "=l"(r) : "f"(lo), "f"(hi));
    return r;
}
__device__ __forceinline__ void fma2(unsigned long long& d,
                                     unsigned long long a, unsigned long long b) {
    asm("fma.rn.f32x2 %0, %1, %2, %0;" : "+l"(d) : "l"(a), "l"(b));
}
__device__ __forceinline__ unsigned long long fma2v(unsigned long long a,
                                                    unsigned long long b,
                                                    unsigned long long c) {
    unsigned long long d;
    asm("fma.rn.f32x2 %0, %1, %2, %3;" : "=l"(d) : "l"(a), "l"(b), "l"(c));
    return d;
}
__device__ __forceinline__ unsigned long long mul2(unsigned long long a,
                                                   unsigned long long b) {
    unsigned long long d;
    asm("mul.rn.f32x2 %0, %1, %2;" : "=l"(d) : "l"(a), "l"(b));
    return d;
}
__device__ __forceinline__ unsigned long long add2(unsigned long long a,
                                                   unsigned long long b) {
    unsigned long long d;
    asm("add.rn.f32x2 %0, %1, %2;" : "=l"(d) : "l"(a), "l"(b));
    return d;
}
__device__ __forceinline__ float2 up2(unsigned long long v) {
    float lo, hi;
    asm("mov.b64 {%0, %1}, %2;" : "=f"(lo), "=f"(hi) : "l"(v));
    return make_float2(lo, hi);
}

// ---------------------------------------------------------------------------
// Kernel 1: FPS (blocks 0..15, one per batch) + points-transpose (blocks 16..143)
// FPS: 512 threads, 8 pts/thread. Packed f32x2 distance updates (bit-identical
// values to the scalar fmaf form). Per-warp argmax via redux.sync; cross-warp
// reduce by warp 0 only (u64 keys: (dist bits << 32) | ~idx, max == argmax
// with lowest-index tiebreak, matching jnp.argmax).
// ---------------------------------------------------------------------------
constexpr int FPS_SMEM_BYTES = 3 * Nn * 4 + 16 * 8 + 4 * 4 + 64;

__global__ __launch_bounds__(512) void fps_prep_kernel(const float* __restrict__ xyz,
                                                       const float* __restrict__ pts,
                                                       float* __restrict__ out_xyz)
{
    extern __shared__ float dsm[];
    int t = threadIdx.x;

    if (blockIdx.x >= 16) {
        // ---- transpose blocks: (B,CP,N) -> (B,N,CP), 512-wide n-chunks ----
        float (*tile)[33] = (float (*)[33])dsm;
        int bx = blockIdx.x - 16;
        int b  = bx >> 3;
        int n0 = (bx & 7) * 512;
        int txx = t & 31, tyy = t >> 5;   // tyy 0..15
        const float* src = pts + (size_t)b * CPn * Nn;
        float* dst = g_ptsT + (size_t)b * Nn * CPn;
        for (int ct = 0; ct < 2; ct++) {
            int c0 = ct * 32;
            for (int nt = 0; nt < 16; nt++) {
                int nn0 = n0 + nt * 32;
                tile[tyy][txx]      = src[(size_t)(c0 + tyy) * Nn + nn0 + txx];
                tile[tyy + 16][txx] = src[(size_t)(c0 + tyy + 16) * Nn + nn0 + txx];
                __syncthreads();
                dst[(size_t)(nn0 + tyy) * CPn + c0 + txx]      = tile[txx][tyy];
                dst[(size_t)(nn0 + tyy + 16) * CPn + c0 + txx] = tile[txx][tyy + 16];
                __syncthreads();
            }
        }
        return;
    }

    // ---- FPS blocks ----
    float* sx = dsm;
    float* sy = dsm + Nn;
    float* sz = dsm + 2 * Nn;
    unsigned long long* skey = (unsigned long long*)(dsm + 3 * Nn);
    float* s_c = dsm + 3 * Nn + 32;   // 3 floats (after 16 u64 keys)

    int b = blockIdx.x;
    const float* xb = xyz + (size_t)b * Nn * 3;

    // pair layout: pair i holds points (t + 2i*512) [lo] and (t + (2i+1)*512) [hi]
    unsigned long long px2[4], py2[4], pz2[4];
    float dist[8];
#pragma unroll
    for (int i = 0; i < 4; i++) {
        int j0 = t + (2 * i) * 512;
        int j1 = t + (2 * i + 1) * 512;
        float x0 = xb[3 * j0], y0 = xb[3 * j0 + 1], z0 = xb[3 * j0 + 2];
        float x1 = xb[3 * j1], y1 = xb[3 * j1 + 1], z1 = xb[3 * j1 + 2];
        px2[i] = pk2(x0, x1);
        py2[i] = pk2(y0, y1);
        pz2[i] = pk2(z0, z1);
        sx[j0] = x0; sy[j0] = y0; sz[j0] = z0;
        sx[j1] = x1; sy[j1] = y1; sz[j1] = z1;
        dist[2 * i] = 1e10f; dist[2 * i + 1] = 1e10f;
    }
    __syncthreads();

    float cx = sx[0], cy = sy[0], cz = sz[0];
    if (t == 0) {
        float* o = out_xyz + (size_t)b * Sn * 3;
        o[0] = cx; o[1] = cy; o[2] = cz;
    }

    const unsigned FULL = 0xffffffffu;
    int lane = t & 31, wid = t >> 5;

    for (int it = 1; it < Sn; ++it) {
        unsigned long long ncx2 = pk2(-cx, -cx);
        unsigned long long ncy2 = pk2(-cy, -cy);
        unsigned long long ncz2 = pk2(-cz, -cz);
#pragma unroll
        for (int i = 0; i < 4; i++) {
            unsigned long long dx = add2(px2[i], ncx2);
            unsigned long long dy = add2(py2[i], ncy2);
            unsigned long long dz = add2(pz2[i], ncz2);
            unsigned long long d2 = mul2(dx, dx);
            d2 = fma2v(dy, dy, d2);
            d2 = fma2v(dz, dz, d2);
            float2 dd = up2(d2);
            dist[2 * i]     = fminf(dist[2 * i], dd.x);
            dist[2 * i + 1] = fminf(dist[2 * i + 1], dd.y);
        }
        // local max (tree), then lowest-slot equality scan for the index
        float mv = fmaxf(fmaxf(fmaxf(dist[0], dist[1]), fmaxf(dist[2], dist[3])),
                         fmaxf(fmaxf(dist[4], dist[5]), fmaxf(dist[6], dist[7])));
        int mi = t;
#pragma unroll
        for (int s = 7; s >= 0; s--)
            if (dist[s] == mv) mi = t + s * 512;   // downward scan -> lowest idx

        // warp argmax via redux (dist >= 0 so fp32 bits are order-preserving)
        unsigned db = __float_as_uint(mv);
        unsigned wm = __reduce_max_sync(FULL, db);
        unsigned ci = (db == wm) ? (unsigned)mi : 0xffffffffu;
        unsigned wi = __reduce_min_sync(FULL, ci);
        if (lane == 0)
            skey[wid] = ((unsigned long long)wm << 32) | (unsigned)(~wi);
        __syncthreads();

        // cross-warp reduce: warp 0 only (lanes 0-15 hold keys; xor-reduce)
        if (t < 32) {
            unsigned long long k = (lane < 16) ? skey[lane] : 0ull;
#pragma unroll
            for (int off = 8; off; off >>= 1) {
                unsigned long long ok = __shfl_xor_sync(FULL, k, off);
                if (ok > k) k = ok;
            }
            if (lane < 3) {
                int far = ~(unsigned)k;
                const float* col = (lane == 0) ? sx : ((lane == 1) ? sy : sz);
                float v = col[far];
                s_c[lane] = v;
                out_xyz[((size_t)b * Sn + it) * 3 + lane] = v;
            }
        }
        __syncthreads();
        cx = s_c[0]; cy = s_c[1]; cz = s_c[2];
    }
}

// ---------------------------------------------------------------------------
// Kernel 2: kNN — warp per centroid, warp-collective sorted top-32.
// ---------------------------------------------------------------------------
__global__ __launch_bounds__(256) void knn_kernel(const float* __restrict__ xyz,
                                                  const float* __restrict__ new_xyz)
{
    extern __shared__ float4 sp[];   // 4096 x (x,y,z,|p|^2) = 64KB
    int b = blockIdx.y;
    const float* xb = xyz + (size_t)b * Nn * 3;
    for (int j = threadIdx.x; j < Nn; j += 256) {
        float x = xb[3 * j], y = xb[3 * j + 1], z = xb[3 * j + 2];
        sp[j] = make_float4(x, y, z, fmaf(z, z, fmaf(y, y, x * x)));
    }
    __syncthreads();

    const unsigned FULL = 0xffffffffu;
    int warp = threadIdx.x >> 5, lane = threadIdx.x & 31;
    const float INF = __int_as_float(0x7f800000);

    for (int cc = 0; cc < 8; cc++) {
        int s = blockIdx.x * 64 + cc * 8 + warp;
        const float* cp = new_xyz + ((size_t)b * Sn + s) * 3;
        float nx = cp[0], ny = cp[1], nz = cp[2];
        float cn = fmaf(nz, nz, fmaf(ny, ny, nx * nx));

        float cur_d = INF; int cur_i = 0x7fffffff;
        float wmax = INF;

        for (int j0 = 0; j0 < Nn; j0 += 32) {
            float4 p = sp[j0 + lane];
            float dot = fmaf(nz, p.z, fmaf(ny, p.y, nx * p.x));
            float d = (cn + p.w) - 2.0f * dot;
            unsigned mask = __ballot_sync(FULL, d <= wmax);
            while (mask) {
                int src = __ffs(mask) - 1;
                mask &= mask - 1;
                float dn = __shfl_sync(FULL, d, src);
                int   ix = j0 + src;
                bool less = (cur_d < dn) || (cur_d == dn && cur_i < ix);
                int pos = __popc(__ballot_sync(FULL, less));
                if (pos < 32) {
                    float ud = __shfl_up_sync(FULL, cur_d, 1);
                    int   ui = __shfl_up_sync(FULL, cur_i, 1);
                    if (lane > pos)       { cur_d = ud; cur_i = ui; }
                    else if (lane == pos) { cur_d = dn; cur_i = ix; }
                    wmax = __shfl_sync(FULL, cur_d, 31);
                }
            }
        }
        g_knn[((b * Sn + s) << 5) + lane] = cur_i;
    }
}

// ---------------------------------------------------------------------------
// Kernel 3: fused gather + 3-layer MLP + maxpool with packed FFMA2.
// ---------------------------------------------------------------------------
constexpr int ST       = 260;
constexpr int OFF_W1T  = 0;
constexpr int OFF_W2T  = OFF_W1T + 67 * 64;      // 4288
constexpr int OFF_W3T  = OFF_W2T + 64 * 64;      // 8384
constexpr int OFF_B1   = OFF_W3T + 64 * 128;     // 16576
constexpr int OFF_B2   = OFF_B1 + 64;
constexpr int OFF_B3   = OFF_B2 + 64;
constexpr int OFF_XT   = OFF_B3 + 128;           // 16832
constexpr int OFF_H1   = OFF_XT + 67 * ST;       // 34252
constexpr int SMEM_FLOATS = OFF_H1 + 64 * ST;    // 50892
constexpr int MLP_SMEM_BYTES = SMEM_FLOATS * 4;  // 203568

template <int C, int WS>
__device__ __forceinline__ void layer_f32x2(const float* __restrict__ Xs,
                                            const float* __restrict__ Wt,
                                            const float* __restrict__ Bs,
                                            float* __restrict__ Hs,
                                            int p0, int o0)
{
    unsigned long long acc[4][8];
#pragma unroll
    for (int i = 0; i < 4; i++)
#pragma unroll
        for (int o = 0; o < 8; o++) acc[i][o] = pk2(0.0f, 0.0f);

    for (int c = 0; c < C; c++) {
        float4 xv = *(const float4*)(Xs + c * ST + p0);
        const float4* wp = (const float4*)(Wt + c * WS + o0);
        float4 w0 = wp[0], w1 = wp[1], w2 = wp[2], w3 = wp[3];
        unsigned long long xq[4] = {pk2(xv.x, xv.x), pk2(xv.y, xv.y),
                                    pk2(xv.z, xv.z), pk2(xv.w, xv.w)};
        unsigned long long wq[8] = {pk2(w0.x, w0.y), pk2(w0.z, w0.w),
                                    pk2(w1.x, w1.y), pk2(w1.z, w1.w),
                                    pk2(w2.x, w2.y), pk2(w2.z, w2.w),
                                    pk2(w3.x, w3.y), pk2(w3.z, w3.w)};
#pragma unroll
        for (int i = 0; i < 4; i++)
#pragma unroll
            for (int o = 0; o < 8; o++) fma2(acc[i][o], xq[i], wq[o]);
    }
#pragma unroll
    for (int o = 0; o < 8; o++) {
        float b0 = Bs[o0 + 2 * o], b1 = Bs[o0 + 2 * o + 1];
        float2 a0 = up2(acc[0][o]), a1 = up2(acc[1][o]);
        float2 a2 = up2(acc[2][o]), a3 = up2(acc[3][o]);
        float4 ve = make_float4(fmaxf(a0.x + b0, 0.f), fmaxf(a1.x + b0, 0.f),
                                fmaxf(a2.x + b0, 0.f), fmaxf(a3.x + b0, 0.f));
        float4 vo = make_float4(fmaxf(a0.y + b1, 0.f), fmaxf(a1.y + b1, 0.f),
                                fmaxf(a2.y + b1, 0.f), fmaxf(a3.y + b1, 0.f));
        *(float4*)(Hs + (o0 + 2 * o) * ST + p0)     = ve;
        *(float4*)(Hs + (o0 + 2 * o + 1) * ST + p0) = vo;
    }
}

__global__ __launch_bounds__(256) void mlp_kernel(
    const float* __restrict__ xyz,
    const float* __restrict__ W1, const float* __restrict__ b1,
    const float* __restrict__ W2, const float* __restrict__ b2,
    const float* __restrict__ W3, const float* __restrict__ b3,
    float* __restrict__ out_np)
{
    extern __shared__ float sm[];
    float* sW1t = sm + OFF_W1T;
    float* sW2t = sm + OFF_W2T;
    float* sW3t = sm + OFF_W3T;
    float* sB1  = sm + OFF_B1;
    float* sB2  = sm + OFF_B2;
    float* sB3  = sm + OFF_B3;
    float* sXt  = sm + OFF_XT;
    float* sH1  = sm + OFF_H1;
    float* sH2  = sXt;  // alias: X dead after layer 1

    int tid = threadIdx.x;
    int b   = blockIdx.y;
    int s0  = blockIdx.x * 8;

    for (int i = tid; i < 64 * 67; i += 256) { int o = i / 67, c = i % 67; sW1t[c * 64 + o] = W1[i]; }
    for (int i = tid; i < 64 * 64; i += 256) { int o = i >> 6, c = i & 63; sW2t[c * 64 + o] = W2[i]; }
    for (int i = tid; i < 128 * 64; i += 256){ int o = i >> 6, c = i & 63; sW3t[c * 128 + o] = W3[i]; }
    if (tid < 64)  sB1[tid] = b1[tid];
    if (tid < 64)  sB2[tid] = b2[tid];
    if (tid < 128) sB3[tid] = b3[tid];

    // gather: Xt[c][p], channels 0..2 = neighbor xyz, 3..66 = point features
    {
        int wid = tid >> 5, lane = tid & 31;
        for (int p = wid; p < 256; p += 8) {
            int s = s0 + (p >> 5);
            int j = g_knn[((b * Sn + s) << 5) + (p & 31)];
            const float* pr = g_ptsT + ((size_t)(b * Nn + j)) * CPn;
            float v0 = (lane < 3) ? xyz[((size_t)(b * Nn + j)) * 3 + lane] : pr[lane - 3];
            sXt[lane * ST + p]        = v0;
            sXt[(lane + 32) * ST + p] = pr[lane + 29];
            if (lane < 3) sXt[(lane + 64) * ST + p] = pr[lane + 61];
        }
    }
    __syncthreads();

    int tx = tid & 63, ty = tid >> 6;
    int p0 = tx * 4;

    layer_f32x2<67, 64>(sXt, sW1t, sB1, sH1, p0, ty * 16);
    __syncthreads();
    layer_f32x2<64, 64>(sH1, sW2t, sB2, sH2, p0, ty * 16);
    __syncthreads();

    // layer 3: 64 -> 128 + maxpool over k (bias/relu monotone: max first)
    {
        int q  = tx & 7;        // 8 threads per centroid (4 points each)
        int sl = tx >> 3;       // local centroid 0..7
        for (int pass = 0; pass < 2; pass++) {
            int o0 = ty * 16 + pass * 64;
            unsigned long long acc[4][8];
#pragma unroll
            for (int i = 0; i < 4; i++)
#pragma unroll
                for (int o = 0; o < 8; o++) acc[i][o] = pk2(0.0f, 0.0f);

            for (int c = 0; c < 64; c++) {
                float4 xv = *(const float4*)(sH2 + c * ST + p0);
                const float4* wp = (const float4*)(sW3t + c * 128 + o0);
                float4 w0 = wp[0], w1 = wp[1], w2 = wp[2], w3 = wp[3];
                unsigned long long xq[4] = {pk2(xv.x, xv.x), pk2(xv.y, xv.y),
                                            pk2(xv.z, xv.z), pk2(xv.w, xv.w)};
                unsigned long long wq[8] = {pk2(w0.x, w0.y), pk2(w0.z, w0.w),
                                            pk2(w1.x, w1.y), pk2(w1.z, w1.w),
                                            pk2(w2.x, w2.y), pk2(w2.z, w2.w),
                                            pk2(w3.x, w3.y), pk2(w3.z, w3.w)};
#pragma unroll
                for (int i = 0; i < 4; i++)
#pragma unroll
                    for (int o = 0; o < 8; o++) fma2(acc[i][o], xq[i], wq[o]);
            }
#pragma unroll
            for (int o = 0; o < 8; o++) {
                float b0 = sB3[o0 + 2 * o], b1v = sB3[o0 + 2 * o + 1];
                float2 a0 = up2(acc[0][o]), a1 = up2(acc[1][o]);
                float2 a2 = up2(acc[2][o]), a3 = up2(acc[3][o]);
                float me = fmaxf(fmaxf(a0.x, a1.x), fmaxf(a2.x, a3.x));
                float mo = fmaxf(fmaxf(a0.y, a1.y), fmaxf(a2.y, a3.y));
                me = fmaxf(me + b0, 0.0f);
                mo = fmaxf(mo + b1v, 0.0f);
#pragma unroll
                for (int off = 1; off < 8; off <<= 1) {
                    me = fmaxf(me, __shfl_xor_sync(0xffffffffu, me, off));
                    mo = fmaxf(mo, __shfl_xor_sync(0xffffffffu, mo, off));
                }
                if (q == 0) {
                    out_np[((size_t)b * C3n + (o0 + 2 * o)) * Sn + (s0 + sl)]     = me;
                    out_np[((size_t)b * C3n + (o0 + 2 * o + 1)) * Sn + (s0 + sl)] = mo;
                }
            }
        }
    }
}

// ---------------------------------------------------------------------------
extern "C" void kernel_launch(void* const* d_in, const int* in_sizes, int n_in,
                              void* d_out, int out_size)
{
    (void)in_sizes; (void)n_in; (void)out_size;
    const float* xyz = (const float*)d_in[0];
    const float* pts = (const float*)d_in[1];
    const float* W1  = (const float*)d_in[2];
    const float* b1  = (const float*)d_in[3];
    const float* W2  = (const float*)d_in[4];
    const float* b2  = (const float*)d_in[5];
    const float* W3  = (const float*)d_in[6];
    const float* b3  = (const float*)d_in[7];

    float* out      = (float*)d_out;
    float* out_xyz  = out;                       // (B,S,3)
    float* out_np   = out + (size_t)Bn * Sn * 3; // (B,128,S)

    cudaFuncSetAttribute(fps_prep_kernel, cudaFuncAttributeMaxDynamicSharedMemorySize, FPS_SMEM_BYTES);
    cudaFuncSetAttribute(knn_kernel, cudaFuncAttributeMaxDynamicSharedMemorySize, Nn * 16);
    cudaFuncSetAttribute(mlp_kernel, cudaFuncAttributeMaxDynamicSharedMemorySize, MLP_SMEM_BYTES);

    fps_prep_kernel<<<16 + 128, 512, FPS_SMEM_BYTES>>>(xyz, pts, out_xyz);
    knn_kernel<<<dim3(Sn / 64, Bn), 256, Nn * 16>>>(xyz, out_xyz);
    mlp_kernel<<<dim3(Sn / 8, Bn), 256, MLP_SMEM_BYTES>>>(xyz, W1, b1, W2, b2, W3, b3, out_np);
}

// round 5
// speedup vs baseline: 1.7650x; 1.1021x over previous
#include <cuda_runtime.h>

// Problem constants (fixed shapes per problem spec)
namespace {
constexpr int Bn  = 16;
constexpr int Nn  = 4096;
constexpr int Sn  = 1024;
constexpr int Kn  = 32;
constexpr int CPn = 64;   // point feature channels
constexpr int C3n = 128;  // final MLP out channels
}

// Scratch (static device arrays; no allocation)
__device__ int   g_knn[Bn * Sn * Kn];
__device__ float g_ptsT[(size_t)Bn * Nn * CPn];  // points transposed to (B,N,CP)

// ---------------------------------------------------------------------------
// f32x2 packed-math helpers
// ---------------------------------------------------------------------------
__device__ __forceinline__ unsigned long long pk2(float lo, float hi) {
    unsigned long long r;
    asm("mov.b64 %0, {%1, %2};" : "=l"(r) : "f"(lo), "f"(hi));
    return r;
}
__device__ __forceinline__ void fma2(unsigned long long& d,
                                     unsigned long long a, unsigned long long b) {
    asm("fma.rn.f32x2 %0, %1, %2, %0;" : "+l"(d) : "l"(a), "l"(b));
}
__device__ __forceinline__ unsigned long long fma2v(unsigned long long a,
                                                    unsigned long long b,
                                                    unsigned long long c) {
    unsigned long long d;
    asm("fma.rn.f32x2 %0, %1, %2, %3;" : "=l"(d) : "l"(a), "l"(b), "l"(c));
    return d;
}
__device__ __forceinline__ unsigned long long mul2(unsigned long long a,
                                                   unsigned long long b) {
    unsigned long long d;
    asm("mul.rn.f32x2 %0, %1, %2;" : "=l"(d) : "l"(a), "l"(b));
    return d;
}
__device__ __forceinline__ unsigned long long add2(unsigned long long a,
                                                   unsigned long long b) {
    unsigned long long d;
    asm("add.rn.f32x2 %0, %1, %2;" : "=l"(d) : "l"(a), "l"(b));
    return d;
}
__device__ __forceinline__ float2 up2(unsigned long long v) {
    float lo, hi;
    asm("mov.b64 {%0, %1}, %2;" : "=f"(lo), "=f"(hi) : "l"(v));
    return make_float2(lo, hi);
}

// ---------------------------------------------------------------------------
// Kernel 1: FPS (blocks 0..15, one per batch) + points-transpose (blocks 16..143)
// FPS: 512 threads, 8 pts/thread, packed f32x2 distance updates (bit-identical
// to the scalar fmaf form). Per-warp argmax via redux.sync. ONE barrier per
// iteration: after it, every warp redundantly reduces the 16 per-warp keys
// (LDS broadcast + 4x u64 shfl_xor max) and broadcast-reads the new centroid
// itself. Keys double-buffered by iteration parity (no 2nd barrier needed).
// Key = (dist bits << 32) | ~idx  =>  max == argmax, lowest-index tiebreak.
// ---------------------------------------------------------------------------
constexpr int FPS_SMEM_BYTES = 3 * Nn * 4 + 32 * 8 + 64;

__global__ __launch_bounds__(512) void fps_prep_kernel(const float* __restrict__ xyz,
                                                       const float* __restrict__ pts,
                                                       float* __restrict__ out_xyz)
{
    extern __shared__ float dsm[];
    int t = threadIdx.x;

    if (blockIdx.x >= 16) {
        // ---- transpose blocks: (B,CP,N) -> (B,N,CP), 512-wide n-chunks ----
        float (*tile)[33] = (float (*)[33])dsm;
        int bx = blockIdx.x - 16;
        int b  = bx >> 3;
        int n0 = (bx & 7) * 512;
        int txx = t & 31, tyy = t >> 5;   // tyy 0..15
        const float* src = pts + (size_t)b * CPn * Nn;
        float* dst = g_ptsT + (size_t)b * Nn * CPn;
        for (int ct = 0; ct < 2; ct++) {
            int c0 = ct * 32;
            for (int nt = 0; nt < 16; nt++) {
                int nn0 = n0 + nt * 32;
                tile[tyy][txx]      = src[(size_t)(c0 + tyy) * Nn + nn0 + txx];
                tile[tyy + 16][txx] = src[(size_t)(c0 + tyy + 16) * Nn + nn0 + txx];
                __syncthreads();
                dst[(size_t)(nn0 + tyy) * CPn + c0 + txx]      = tile[txx][tyy];
                dst[(size_t)(nn0 + tyy + 16) * CPn + c0 + txx] = tile[txx][tyy + 16];
                __syncthreads();
            }
        }
        return;
    }

    // ---- FPS blocks ----
    float* sx = dsm;
    float* sy = dsm + Nn;
    float* sz = dsm + 2 * Nn;
    unsigned long long* skey = (unsigned long long*)(dsm + 3 * Nn);  // 2 x 16

    int b = blockIdx.x;
    const float* xb = xyz + (size_t)b * Nn * 3;

    // pair layout: pair i holds points (t + 2i*512) [lo] and (t + (2i+1)*512) [hi]
    unsigned long long px2[4], py2[4], pz2[4];
    float dist[8];
#pragma unroll
    for (int i = 0; i < 4; i++) {
        int j0 = t + (2 * i) * 512;
        int j1 = t + (2 * i + 1) * 512;
        float x0 = xb[3 * j0], y0 = xb[3 * j0 + 1], z0 = xb[3 * j0 + 2];
        float x1 = xb[3 * j1], y1 = xb[3 * j1 + 1], z1 = xb[3 * j1 + 2];
        px2[i] = pk2(x0, x1);
        py2[i] = pk2(y0, y1);
        pz2[i] = pk2(z0, z1);
        sx[j0] = x0; sy[j0] = y0; sz[j0] = z0;
        sx[j1] = x1; sy[j1] = y1; sz[j1] = z1;
        dist[2 * i] = 1e10f; dist[2 * i + 1] = 1e10f;
    }
    __syncthreads();

    float cx = sx[0], cy = sy[0], cz = sz[0];
    if (t == 0) {
        float* o = out_xyz + (size_t)b * Sn * 3;
        o[0] = cx; o[1] = cy; o[2] = cz;
    }

    const unsigned FULL = 0xffffffffu;
    int lane = t & 31, wid = t >> 5;

    for (int it = 1; it < Sn; ++it) {
        unsigned long long ncx2 = pk2(-cx, -cx);
        unsigned long long ncy2 = pk2(-cy, -cy);
        unsigned long long ncz2 = pk2(-cz, -cz);
#pragma unroll
        for (int i = 0; i < 4; i++) {
            unsigned long long dx = add2(px2[i], ncx2);
            unsigned long long dy = add2(py2[i], ncy2);
            unsigned long long dz = add2(pz2[i], ncz2);
            unsigned long long d2 = mul2(dx, dx);
            d2 = fma2v(dy, dy, d2);
            d2 = fma2v(dz, dz, d2);
            float2 dd = up2(d2);
            dist[2 * i]     = fminf(dist[2 * i], dd.x);
            dist[2 * i + 1] = fminf(dist[2 * i + 1], dd.y);
        }
        // local max (tree), then lowest-slot equality scan for the index
        float mv = fmaxf(fmaxf(fmaxf(dist[0], dist[1]), fmaxf(dist[2], dist[3])),
                         fmaxf(fmaxf(dist[4], dist[5]), fmaxf(dist[6], dist[7])));
        int mi = t;
#pragma unroll
        for (int s = 7; s >= 0; s--)
            if (dist[s] == mv) mi = t + s * 512;   // downward scan -> lowest idx

        // warp argmax via redux (dist >= 0 so fp32 bits are order-preserving)
        unsigned db = __float_as_uint(mv);
        unsigned wm = __reduce_max_sync(FULL, db);
        unsigned ci = (db == wm) ? (unsigned)mi : 0xffffffffu;
        unsigned wi = __reduce_min_sync(FULL, ci);
        if (lane == 0)
            skey[(it & 1) * 16 + wid] = ((unsigned long long)wm << 32) | (unsigned)(~wi);
        __syncthreads();

        // every warp reduces the 16 keys redundantly: LDS + 4x u64 shfl_xor max
        unsigned long long k = skey[(it & 1) * 16 + (lane & 15)];
#pragma unroll
        for (int off = 8; off; off >>= 1) {
            unsigned long long ok = __shfl_xor_sync(FULL, k, off);
            if (ok > k) k = ok;
        }
        int far = ~(unsigned)k;
        cx = sx[far]; cy = sy[far]; cz = sz[far];   // broadcast LDS
        if (t == 0) {
            float* o = out_xyz + ((size_t)b * Sn + it) * 3;
            o[0] = cx; o[1] = cy; o[2] = cz;
        }
    }
}

// ---------------------------------------------------------------------------
// Kernel 2: kNN — warp per centroid, warp-collective sorted top-32.
// ---------------------------------------------------------------------------
__global__ __launch_bounds__(256) void knn_kernel(const float* __restrict__ xyz,
                                                  const float* __restrict__ new_xyz)
{
    extern __shared__ float4 sp[];   // 4096 x (x,y,z,|p|^2) = 64KB
    int b = blockIdx.y;
    const float* xb = xyz + (size_t)b * Nn * 3;
    for (int j = threadIdx.x; j < Nn; j += 256) {
        float x = xb[3 * j], y = xb[3 * j + 1], z = xb[3 * j + 2];
        sp[j] = make_float4(x, y, z, fmaf(z, z, fmaf(y, y, x * x)));
    }
    __syncthreads();

    const unsigned FULL = 0xffffffffu;
    int warp = threadIdx.x >> 5, lane = threadIdx.x & 31;
    const float INF = __int_as_float(0x7f800000);

    for (int cc = 0; cc < 8; cc++) {
        int s = blockIdx.x * 64 + cc * 8 + warp;
        const float* cp = new_xyz + ((size_t)b * Sn + s) * 3;
        float nx = cp[0], ny = cp[1], nz = cp[2];
        float cn = fmaf(nz, nz, fmaf(ny, ny, nx * nx));

        float cur_d = INF; int cur_i = 0x7fffffff;
        float wmax = INF;

        for (int j0 = 0; j0 < Nn; j0 += 32) {
            float4 p = sp[j0 + lane];
            float dot = fmaf(nz, p.z, fmaf(ny, p.y, nx * p.x));
            float d = (cn + p.w) - 2.0f * dot;
            unsigned mask = __ballot_sync(FULL, d <= wmax);
            while (mask) {
                int src = __ffs(mask) - 1;
                mask &= mask - 1;
                float dn = __shfl_sync(FULL, d, src);
                int   ix = j0 + src;
                bool less = (cur_d < dn) || (cur_d == dn && cur_i < ix);
                int pos = __popc(__ballot_sync(FULL, less));
                if (pos < 32) {
                    float ud = __shfl_up_sync(FULL, cur_d, 1);
                    int   ui = __shfl_up_sync(FULL, cur_i, 1);
                    if (lane > pos)       { cur_d = ud; cur_i = ui; }
                    else if (lane == pos) { cur_d = dn; cur_i = ix; }
                    wmax = __shfl_sync(FULL, cur_d, 31);
                }
            }
        }
        g_knn[((b * Sn + s) << 5) + lane] = cur_i;
    }
}

// ---------------------------------------------------------------------------
// Kernel 3: fused gather + 3-layer MLP + maxpool with packed FFMA2.
// Weight pairs loaded straight from SMEM as ulonglong2 (no repacking).
// ---------------------------------------------------------------------------
constexpr int ST       = 260;
constexpr int OFF_W1T  = 0;
constexpr int OFF_W2T  = OFF_W1T + 67 * 64;      // 4288
constexpr int OFF_W3T  = OFF_W2T + 64 * 64;      // 8384
constexpr int OFF_B1   = OFF_W3T + 64 * 128;     // 16576
constexpr int OFF_B2   = OFF_B1 + 64;
constexpr int OFF_B3   = OFF_B2 + 64;
constexpr int OFF_XT   = OFF_B3 + 128;           // 16832
constexpr int OFF_H1   = OFF_XT + 67 * ST;       // 34252
constexpr int SMEM_FLOATS = OFF_H1 + 64 * ST;    // 50892
constexpr int MLP_SMEM_BYTES = SMEM_FLOATS * 4;  // 203568

template <int C, int WS>
__device__ __forceinline__ void layer_f32x2(const float* __restrict__ Xs,
                                            const float* __restrict__ Wt,
                                            const float* __restrict__ Bs,
                                            float* __restrict__ Hs,
                                            int p0, int o0)
{
    unsigned long long acc[4][8];
#pragma unroll
    for (int i = 0; i < 4; i++)
#pragma unroll
        for (int o = 0; o < 8; o++) acc[i][o] = pk2(0.0f, 0.0f);

    for (int c = 0; c < C; c++) {
        float4 xv = *(const float4*)(Xs + c * ST + p0);
        const ulonglong2* wp = (const ulonglong2*)(Wt + c * WS + o0);
        ulonglong2 wa = wp[0], wb = wp[1], wc = wp[2], wd = wp[3];
        unsigned long long xq[4] = {pk2(xv.x, xv.x), pk2(xv.y, xv.y),
                                    pk2(xv.z, xv.z), pk2(xv.w, xv.w)};
        unsigned long long wq[8] = {wa.x, wa.y, wb.x, wb.y,
                                    wc.x, wc.y, wd.x, wd.y};
#pragma unroll
        for (int i = 0; i < 4; i++)
#pragma unroll
            for (int o = 0; o < 8; o++) fma2(acc[i][o], xq[i], wq[o]);
    }
#pragma unroll
    for (int o = 0; o < 8; o++) {
        float b0 = Bs[o0 + 2 * o], b1 = Bs[o0 + 2 * o + 1];
        float2 a0 = up2(acc[0][o]), a1 = up2(acc[1][o]);
        float2 a2 = up2(acc[2][o]), a3 = up2(acc[3][o]);
        float4 ve = make_float4(fmaxf(a0.x + b0, 0.f), fmaxf(a1.x + b0, 0.f),
                                fmaxf(a2.x + b0, 0.f), fmaxf(a3.x + b0, 0.f));
        float4 vo = make_float4(fmaxf(a0.y + b1, 0.f), fmaxf(a1.y + b1, 0.f),
                                fmaxf(a2.y + b1, 0.f), fmaxf(a3.y + b1, 0.f));
        *(float4*)(Hs + (o0 + 2 * o) * ST + p0)     = ve;
        *(float4*)(Hs + (o0 + 2 * o + 1) * ST + p0) = vo;
    }
}

__global__ __launch_bounds__(256) void mlp_kernel(
    const float* __restrict__ xyz,
    const float* __restrict__ W1, const float* __restrict__ b1,
    const float* __restrict__ W2, const float* __restrict__ b2,
    const float* __restrict__ W3, const float* __restrict__ b3,
    float* __restrict__ out_np)
{
    extern __shared__ float sm[];
    float* sW1t = sm + OFF_W1T;
    float* sW2t = sm + OFF_W2T;
    float* sW3t = sm + OFF_W3T;
    float* sB1  = sm + OFF_B1;
    float* sB2  = sm + OFF_B2;
    float* sB3  = sm + OFF_B3;
    float* sXt  = sm + OFF_XT;
    float* sH1  = sm + OFF_H1;
    float* sH2  = sXt;  // alias: X dead after layer 1

    int tid = threadIdx.x;
    int b   = blockIdx.y;
    int s0  = blockIdx.x * 8;

    for (int i = tid; i < 64 * 67; i += 256) { int o = i / 67, c = i % 67; sW1t[c * 64 + o] = W1[i]; }
    for (int i = tid; i < 64 * 64; i += 256) { int o = i >> 6, c = i & 63; sW2t[c * 64 + o] = W2[i]; }
    for (int i = tid; i < 128 * 64; i += 256){ int o = i >> 6, c = i & 63; sW3t[c * 128 + o] = W3[i]; }
    if (tid < 64)  sB1[tid] = b1[tid];
    if (tid < 64)  sB2[tid] = b2[tid];
    if (tid < 128) sB3[tid] = b3[tid];

    // gather: Xt[c][p], channels 0..2 = neighbor xyz, 3..66 = point features
    {
        int wid = tid >> 5, lane = tid & 31;
        for (int p = wid; p < 256; p += 8) {
            int s = s0 + (p >> 5);
            int j = g_knn[((b * Sn + s) << 5) + (p & 31)];
            const float* pr = g_ptsT + ((size_t)(b * Nn + j)) * CPn;
            float v0 = (lane < 3) ? xyz[((size_t)(b * Nn + j)) * 3 + lane] : pr[lane - 3];
            sXt[lane * ST + p]        = v0;
            sXt[(lane + 32) * ST + p] = pr[lane + 29];
            if (lane < 3) sXt[(lane + 64) * ST + p] = pr[lane + 61];
        }
    }
    __syncthreads();

    int tx = tid & 63, ty = tid >> 6;
    int p0 = tx * 4;

    layer_f32x2<67, 64>(sXt, sW1t, sB1, sH1, p0, ty * 16);
    __syncthreads();
    layer_f32x2<64, 64>(sH1, sW2t, sB2, sH2, p0, ty * 16);
    __syncthreads();

    // layer 3: 64 -> 128 + maxpool over k (bias/relu monotone: max first)
    {
        int q  = tx & 7;        // 8 threads per centroid (4 points each)
        int sl = tx >> 3;       // local centroid 0..7
        for (int pass = 0; pass < 2; pass++) {
            int o0 = ty * 16 + pass * 64;
            unsigned long long acc[4][8];
#pragma unroll
            for (int i = 0; i < 4; i++)
#pragma unroll
                for (int o = 0; o < 8; o++) acc[i][o] = pk2(0.0f, 0.0f);

            for (int c = 0; c < 64; c++) {
                float4 xv = *(const float4*)(sH2 + c * ST + p0);
                const ulonglong2* wp = (const ulonglong2*)(sW3t + c * 128 + o0);
                ulonglong2 wa = wp[0], wb = wp[1], wc = wp[2], wd = wp[3];
                unsigned long long xq[4] = {pk2(xv.x, xv.x), pk2(xv.y, xv.y),
                                            pk2(xv.z, xv.z), pk2(xv.w, xv.w)};
                unsigned long long wq[8] = {wa.x, wa.y, wb.x, wb.y,
                                            wc.x, wc.y, wd.x, wd.y};
#pragma unroll
                for (int i = 0; i < 4; i++)
#pragma unroll
                    for (int o = 0; o < 8; o++) fma2(acc[i][o], xq[i], wq[o]);
            }
#pragma unroll
            for (int o = 0; o < 8; o++) {
                float b0 = sB3[o0 + 2 * o], b1v = sB3[o0 + 2 * o + 1];
                float2 a0 = up2(acc[0][o]), a1 = up2(acc[1][o]);
                float2 a2 = up2(acc[2][o]), a3 = up2(acc[3][o]);
                float me = fmaxf(fmaxf(a0.x, a1.x), fmaxf(a2.x, a3.x));
                float mo = fmaxf(fmaxf(a0.y, a1.y), fmaxf(a2.y, a3.y));
                me = fmaxf(me + b0, 0.0f);
                mo = fmaxf(mo + b1v, 0.0f);
#pragma unroll
                for (int off = 1; off < 8; off <<= 1) {
                    me = fmaxf(me, __shfl_xor_sync(0xffffffffu, me, off));
                    mo = fmaxf(mo, __shfl_xor_sync(0xffffffffu, mo, off));
                }
                if (q == 0) {
                    out_np[((size_t)b * C3n + (o0 + 2 * o)) * Sn + (s0 + sl)]     = me;
                    out_np[((size_t)b * C3n + (o0 + 2 * o + 1)) * Sn + (s0 + sl)] = mo;
                }
            }
        }
    }
}

// ---------------------------------------------------------------------------
extern "C" void kernel_launch(void* const* d_in, const int* in_sizes, int n_in,
                              void* d_out, int out_size)
{
    (void)in_sizes; (void)n_in; (void)out_size;
    const float* xyz = (const float*)d_in[0];
    const float* pts = (const float*)d_in[1];
    const float* W1  = (const float*)d_in[2];
    const float* b1  = (const float*)d_in[3];
    const float* W2  = (const float*)d_in[4];
    const float* b2  = (const float*)d_in[5];
    const float* W3  = (const float*)d_in[6];
    const float* b3  = (const float*)d_in[7];

    float* out      = (float*)d_out;
    float* out_xyz  = out;                       // (B,S,3)
    float* out_np   = out + (size_t)Bn * Sn * 3; // (B,128,S)

    cudaFuncSetAttribute(fps_prep_kernel, cudaFuncAttributeMaxDynamicSharedMemorySize, FPS_SMEM_BYTES);
    cudaFuncSetAttribute(knn_kernel, cudaFuncAttributeMaxDynamicSharedMemorySize, Nn * 16);
    cudaFuncSetAttribute(mlp_kernel, cudaFuncAttributeMaxDynamicSharedMemorySize, MLP_SMEM_BYTES);

    fps_prep_kernel<<<16 + 128, 512, FPS_SMEM_BYTES>>>(xyz, pts, out_xyz);
    knn_kernel<<<dim3(Sn / 64, Bn), 256, Nn * 16>>>(xyz, out_xyz);
    mlp_kernel<<<dim3(Sn / 8, Bn), 256, MLP_SMEM_BYTES>>>(xyz, W1, b1, W2, b2, W3, b3, out_np);
}

// round 6
// speedup vs baseline: 1.8649x; 1.0566x over previous
#include <cuda_runtime.h>

// Problem constants (fixed shapes per problem spec)
namespace {
constexpr int Bn  = 16;
constexpr int Nn  = 4096;
constexpr int Sn  = 1024;
constexpr int Kn  = 32;
constexpr int CPn = 64;   // point feature channels
constexpr int C3n = 128;  // final MLP out channels
}

// Scratch (static device arrays; no allocation)
__device__ int   g_knn[Bn * Sn * Kn];
__device__ float g_ptsT[(size_t)Bn * Nn * CPn];  // points transposed to (B,N,CP)

// ---------------------------------------------------------------------------
// f32x2 packed-math helpers
// ---------------------------------------------------------------------------
__device__ __forceinline__ unsigned long long pk2(float lo, float hi) {
    unsigned long long r;
    asm("mov.b64 %0, {%1, %2};" : "=l"(r) : "f"(lo), "f"(hi));
    return r;
}
__device__ __forceinline__ void fma2(unsigned long long& d,
                                     unsigned long long a, unsigned long long b) {
    asm("fma.rn.f32x2 %0, %1, %2, %0;" : "+l"(d) : "l"(a), "l"(b));
}
__device__ __forceinline__ unsigned long long fma2v(unsigned long long a,
                                                    unsigned long long b,
                                                    unsigned long long c) {
    unsigned long long d;
    asm("fma.rn.f32x2 %0, %1, %2, %3;" : "=l"(d) : "l"(a), "l"(b), "l"(c));
    return d;
}
__device__ __forceinline__ unsigned long long mul2(unsigned long long a,
                                                   unsigned long long b) {
    unsigned long long d;
    asm("mul.rn.f32x2 %0, %1, %2;" : "=l"(d) : "l"(a), "l"(b));
    return d;
}
__device__ __forceinline__ unsigned long long add2(unsigned long long a,
                                                   unsigned long long b) {
    unsigned long long d;
    asm("add.rn.f32x2 %0, %1, %2;" : "=l"(d) : "l"(a), "l"(b));
    return d;
}
__device__ __forceinline__ float2 up2(unsigned long long v) {
    float lo, hi;
    asm("mov.b64 {%0, %1}, %2;" : "=f"(lo), "=f"(hi) : "l"(v));
    return make_float2(lo, hi);
}

// ---------------------------------------------------------------------------
// Kernel 1: FPS (blocks 0..15, one per batch) + points-transpose (blocks 16..143)
// FPS: 512 threads, 8 pts/thread, packed f32x2 distance updates. ONE barrier
// per iteration. Cross-warp argmax after the barrier is done redundantly by
// every warp with two 32-bit redux.sync ops over the 16 per-warp winners:
//   max over dist bits (d >= 0 -> bit order == float order), then
//   min over equality-filtered indices (lowest-index tiebreak, = jnp.argmax).
// Winner slots double-buffered by iteration parity (no 2nd barrier).
// ---------------------------------------------------------------------------
constexpr int FPS_SMEM_BYTES = 3 * Nn * 4 + 64 * 4 + 64;

__global__ __launch_bounds__(512) void fps_prep_kernel(const float* __restrict__ xyz,
                                                       const float* __restrict__ pts,
                                                       float* __restrict__ out_xyz)
{
    extern __shared__ float dsm[];
    int t = threadIdx.x;

    if (blockIdx.x >= 16) {
        // ---- transpose blocks: (B,CP,N) -> (B,N,CP), 512-wide n-chunks ----
        float (*tile)[33] = (float (*)[33])dsm;
        int bx = blockIdx.x - 16;
        int b  = bx >> 3;
        int n0 = (bx & 7) * 512;
        int txx = t & 31, tyy = t >> 5;   // tyy 0..15
        const float* src = pts + (size_t)b * CPn * Nn;
        float* dst = g_ptsT + (size_t)b * Nn * CPn;
        for (int ct = 0; ct < 2; ct++) {
            int c0 = ct * 32;
            for (int nt = 0; nt < 16; nt++) {
                int nn0 = n0 + nt * 32;
                tile[tyy][txx]      = src[(size_t)(c0 + tyy) * Nn + nn0 + txx];
                tile[tyy + 16][txx] = src[(size_t)(c0 + tyy + 16) * Nn + nn0 + txx];
                __syncthreads();
                dst[(size_t)(nn0 + tyy) * CPn + c0 + txx]      = tile[txx][tyy];
                dst[(size_t)(nn0 + tyy + 16) * CPn + c0 + txx] = tile[txx][tyy + 16];
                __syncthreads();
            }
        }
        return;
    }

    // ---- FPS blocks ----
    float* sx = dsm;
    float* sy = dsm + Nn;
    float* sz = dsm + 2 * Nn;
    unsigned* sdist = (unsigned*)(dsm + 3 * Nn);   // 2 parities x 16
    unsigned* sidx  = sdist + 32;                  // 2 parities x 16

    int b = blockIdx.x;
    const float* xb = xyz + (size_t)b * Nn * 3;

    // pair layout: pair i holds points (t + 2i*512) [lo] and (t + (2i+1)*512) [hi]
    unsigned long long px2[4], py2[4], pz2[4];
    float dist[8];
#pragma unroll
    for (int i = 0; i < 4; i++) {
        int j0 = t + (2 * i) * 512;
        int j1 = t + (2 * i + 1) * 512;
        float x0 = xb[3 * j0], y0 = xb[3 * j0 + 1], z0 = xb[3 * j0 + 2];
        float x1 = xb[3 * j1], y1 = xb[3 * j1 + 1], z1 = xb[3 * j1 + 2];
        px2[i] = pk2(x0, x1);
        py2[i] = pk2(y0, y1);
        pz2[i] = pk2(z0, z1);
        sx[j0] = x0; sy[j0] = y0; sz[j0] = z0;
        sx[j1] = x1; sy[j1] = y1; sz[j1] = z1;
        dist[2 * i] = 1e10f; dist[2 * i + 1] = 1e10f;
    }
    __syncthreads();

    float cx = sx[0], cy = sy[0], cz = sz[0];
    if (t == 0) {
        float* o = out_xyz + (size_t)b * Sn * 3;
        o[0] = cx; o[1] = cy; o[2] = cz;
    }

    const unsigned FULL = 0xffffffffu;
    int lane = t & 31, wid = t >> 5;

    for (int it = 1; it < Sn; ++it) {
        unsigned long long ncx2 = pk2(-cx, -cx);
        unsigned long long ncy2 = pk2(-cy, -cy);
        unsigned long long ncz2 = pk2(-cz, -cz);
#pragma unroll
        for (int i = 0; i < 4; i++) {
            unsigned long long dx = add2(px2[i], ncx2);
            unsigned long long dy = add2(py2[i], ncy2);
            unsigned long long dz = add2(pz2[i], ncz2);
            unsigned long long d2 = mul2(dx, dx);
            d2 = fma2v(dy, dy, d2);
            d2 = fma2v(dz, dz, d2);
            float2 dd = up2(d2);
            dist[2 * i]     = fminf(dist[2 * i], dd.x);
            dist[2 * i + 1] = fminf(dist[2 * i + 1], dd.y);
        }
        // local max (tree), then lowest-slot equality scan for the index
        float mv = fmaxf(fmaxf(fmaxf(dist[0], dist[1]), fmaxf(dist[2], dist[3])),
                         fmaxf(fmaxf(dist[4], dist[5]), fmaxf(dist[6], dist[7])));
        int mi = t;
#pragma unroll
        for (int s = 7; s >= 0; s--)
            if (dist[s] == mv) mi = t + s * 512;   // downward scan -> lowest idx

        // warp argmax via redux (dist >= 0 so fp32 bits are order-preserving)
        unsigned db = __float_as_uint(mv);
        unsigned wm = __reduce_max_sync(FULL, db);
        unsigned ci = (db == wm) ? (unsigned)mi : 0xffffffffu;
        unsigned wi = __reduce_min_sync(FULL, ci);
        int slot = (it & 1) * 16 + wid;
        if (lane == 0) { sdist[slot] = wm; sidx[slot] = wi; }
        __syncthreads();

        // every warp reduces the 16 winners redundantly via 2x 32-bit redux
        int rs = (it & 1) * 16 + (lane & 15);
        unsigned d16 = sdist[rs];
        unsigned i16 = sidx[rs];
        unsigned gm  = __reduce_max_sync(FULL, d16);
        unsigned gc  = (d16 == gm) ? i16 : 0xffffffffu;
        unsigned far = __reduce_min_sync(FULL, gc);
        cx = sx[far]; cy = sy[far]; cz = sz[far];   // broadcast LDS
        if (t == 0) {
            float* o = out_xyz + ((size_t)b * Sn + it) * 3;
            o[0] = cx; o[1] = cy; o[2] = cz;
        }
    }
}

// ---------------------------------------------------------------------------
// Kernel 2: kNN — warp per centroid, warp-collective sorted top-32.
// ---------------------------------------------------------------------------
__global__ __launch_bounds__(256) void knn_kernel(const float* __restrict__ xyz,
                                                  const float* __restrict__ new_xyz)
{
    extern __shared__ float4 sp[];   // 4096 x (x,y,z,|p|^2) = 64KB
    int b = blockIdx.y;
    const float* xb = xyz + (size_t)b * Nn * 3;
    for (int j = threadIdx.x; j < Nn; j += 256) {
        float x = xb[3 * j], y = xb[3 * j + 1], z = xb[3 * j + 2];
        sp[j] = make_float4(x, y, z, fmaf(z, z, fmaf(y, y, x * x)));
    }
    __syncthreads();

    const unsigned FULL = 0xffffffffu;
    int warp = threadIdx.x >> 5, lane = threadIdx.x & 31;
    const float INF = __int_as_float(0x7f800000);

    for (int cc = 0; cc < 8; cc++) {
        int s = blockIdx.x * 64 + cc * 8 + warp;
        const float* cp = new_xyz + ((size_t)b * Sn + s) * 3;
        float nx = cp[0], ny = cp[1], nz = cp[2];
        float cn = fmaf(nz, nz, fmaf(ny, ny, nx * nx));

        float cur_d = INF; int cur_i = 0x7fffffff;
        float wmax = INF;

        for (int j0 = 0; j0 < Nn; j0 += 32) {
            float4 p = sp[j0 + lane];
            float dot = fmaf(nz, p.z, fmaf(ny, p.y, nx * p.x));
            float d = (cn + p.w) - 2.0f * dot;
            unsigned mask = __ballot_sync(FULL, d <= wmax);
            while (mask) {
                int src = __ffs(mask) - 1;
                mask &= mask - 1;
                float dn = __shfl_sync(FULL, d, src);
                int   ix = j0 + src;
                bool less = (cur_d < dn) || (cur_d == dn && cur_i < ix);
                int pos = __popc(__ballot_sync(FULL, less));
                if (pos < 32) {
                    float ud = __shfl_up_sync(FULL, cur_d, 1);
                    int   ui = __shfl_up_sync(FULL, cur_i, 1);
                    if (lane > pos)       { cur_d = ud; cur_i = ui; }
                    else if (lane == pos) { cur_d = dn; cur_i = ix; }
                    wmax = __shfl_sync(FULL, cur_d, 31);
                }
            }
        }
        g_knn[((b * Sn + s) << 5) + lane] = cur_i;
    }
}

// ---------------------------------------------------------------------------
// Kernel 3: fused gather + 3-layer MLP + maxpool with packed FFMA2.
// Weight pairs loaded straight from SMEM as ulonglong2 (no repacking).
// ---------------------------------------------------------------------------
constexpr int ST       = 260;
constexpr int OFF_W1T  = 0;
constexpr int OFF_W2T  = OFF_W1T + 67 * 64;      // 4288
constexpr int OFF_W3T  = OFF_W2T + 64 * 64;      // 8384
constexpr int OFF_B1   = OFF_W3T + 64 * 128;     // 16576
constexpr int OFF_B2   = OFF_B1 + 64;
constexpr int OFF_B3   = OFF_B2 + 64;
constexpr int OFF_XT   = OFF_B3 + 128;           // 16832
constexpr int OFF_H1   = OFF_XT + 67 * ST;       // 34252
constexpr int SMEM_FLOATS = OFF_H1 + 64 * ST;    // 50892
constexpr int MLP_SMEM_BYTES = SMEM_FLOATS * 4;  // 203568

template <int C, int WS>
__device__ __forceinline__ void layer_f32x2(const float* __restrict__ Xs,
                                            const float* __restrict__ Wt,
                                            const float* __restrict__ Bs,
                                            float* __restrict__ Hs,
                                            int p0, int o0)
{
    unsigned long long acc[4][8];
#pragma unroll
    for (int i = 0; i < 4; i++)
#pragma unroll
        for (int o = 0; o < 8; o++) acc[i][o] = pk2(0.0f, 0.0f);

    for (int c = 0; c < C; c++) {
        float4 xv = *(const float4*)(Xs + c * ST + p0);
        const ulonglong2* wp = (const ulonglong2*)(Wt + c * WS + o0);
        ulonglong2 wa = wp[0], wb = wp[1], wc = wp[2], wd = wp[3];
        unsigned long long xq[4] = {pk2(xv.x, xv.x), pk2(xv.y, xv.y),
                                    pk2(xv.z, xv.z), pk2(xv.w, xv.w)};
        unsigned long long wq[8] = {wa.x, wa.y, wb.x, wb.y,
                                    wc.x, wc.y, wd.x, wd.y};
#pragma unroll
        for (int i = 0; i < 4; i++)
#pragma unroll
            for (int o = 0; o < 8; o++) fma2(acc[i][o], xq[i], wq[o]);
    }
#pragma unroll
    for (int o = 0; o < 8; o++) {
        float b0 = Bs[o0 + 2 * o], b1 = Bs[o0 + 2 * o + 1];
        float2 a0 = up2(acc[0][o]), a1 = up2(acc[1][o]);
        float2 a2 = up2(acc[2][o]), a3 = up2(acc[3][o]);
        float4 ve = make_float4(fmaxf(a0.x + b0, 0.f), fmaxf(a1.x + b0, 0.f),
                                fmaxf(a2.x + b0, 0.f), fmaxf(a3.x + b0, 0.f));
        float4 vo = make_float4(fmaxf(a0.y + b1, 0.f), fmaxf(a1.y + b1, 0.f),
                                fmaxf(a2.y + b1, 0.f), fmaxf(a3.y + b1, 0.f));
        *(float4*)(Hs + (o0 + 2 * o) * ST + p0)     = ve;
        *(float4*)(Hs + (o0 + 2 * o + 1) * ST + p0) = vo;
    }
}

__global__ __launch_bounds__(256) void mlp_kernel(
    const float* __restrict__ xyz,
    const float* __restrict__ W1, const float* __restrict__ b1,
    const float* __restrict__ W2, const float* __restrict__ b2,
    const float* __restrict__ W3, const float* __restrict__ b3,
    float* __restrict__ out_np)
{
    extern __shared__ float sm[];
    float* sW1t = sm + OFF_W1T;
    float* sW2t = sm + OFF_W2T;
    float* sW3t = sm + OFF_W3T;
    float* sB1  = sm + OFF_B1;
    float* sB2  = sm + OFF_B2;
    float* sB3  = sm + OFF_B3;
    float* sXt  = sm + OFF_XT;
    float* sH1  = sm + OFF_H1;
    float* sH2  = sXt;  // alias: X dead after layer 1

    int tid = threadIdx.x;
    int b   = blockIdx.y;
    int s0  = blockIdx.x * 8;

    for (int i = tid; i < 64 * 67; i += 256) { int o = i / 67, c = i % 67; sW1t[c * 64 + o] = W1[i]; }
    for (int i = tid; i < 64 * 64; i += 256) { int o = i >> 6, c = i & 63; sW2t[c * 64 + o] = W2[i]; }
    for (int i = tid; i < 128 * 64; i += 256){ int o = i >> 6, c = i & 63; sW3t[c * 128 + o] = W3[i]; }
    if (tid < 64)  sB1[tid] = b1[tid];
    if (tid < 64)  sB2[tid] = b2[tid];
    if (tid < 128) sB3[tid] = b3[tid];

    // gather: Xt[c][p], channels 0..2 = neighbor xyz, 3..66 = point features
    {
        int wid = tid >> 5, lane = tid & 31;
        for (int p = wid; p < 256; p += 8) {
            int s = s0 + (p >> 5);
            int j = g_knn[((b * Sn + s) << 5) + (p & 31)];
            const float* pr = g_ptsT + ((size_t)(b * Nn + j)) * CPn;
            float v0 = (lane < 3) ? xyz[((size_t)(b * Nn + j)) * 3 + lane] : pr[lane - 3];
            sXt[lane * ST + p]        = v0;
            sXt[(lane + 32) * ST + p] = pr[lane + 29];
            if (lane < 3) sXt[(lane + 64) * ST + p] = pr[lane + 61];
        }
    }
    __syncthreads();

    int tx = tid & 63, ty = tid >> 6;
    int p0 = tx * 4;

    layer_f32x2<67, 64>(sXt, sW1t, sB1, sH1, p0, ty * 16);
    __syncthreads();
    layer_f32x2<64, 64>(sH1, sW2t, sB2, sH2, p0, ty * 16);
    __syncthreads();

    // layer 3: 64 -> 128 + maxpool over k (bias/relu monotone: max first)
    {
        int q  = tx & 7;        // 8 threads per centroid (4 points each)
        int sl = tx >> 3;       // local centroid 0..7
        for (int pass = 0; pass < 2; pass++) {
            int o0 = ty * 16 + pass * 64;
            unsigned long long acc[4][8];
#pragma unroll
            for (int i = 0; i < 4; i++)
#pragma unroll
                for (int o = 0; o < 8; o++) acc[i][o] = pk2(0.0f, 0.0f);

            for (int c = 0; c < 64; c++) {
                float4 xv = *(const float4*)(sH2 + c * ST + p0);
                const ulonglong2* wp = (const ulonglong2*)(sW3t + c * 128 + o0);
                ulonglong2 wa = wp[0], wb = wp[1], wc = wp[2], wd = wp[3];
                unsigned long long xq[4] = {pk2(xv.x, xv.x), pk2(xv.y, xv.y),
                                            pk2(xv.z, xv.z), pk2(xv.w, xv.w)};
                unsigned long long wq[8] = {wa.x, wa.y, wb.x, wb.y,
                                            wc.x, wc.y, wd.x, wd.y};
#pragma unroll
                for (int i = 0; i < 4; i++)
#pragma unroll
                    for (int o = 0; o < 8; o++) fma2(acc[i][o], xq[i], wq[o]);
            }
#pragma unroll
            for (int o = 0; o < 8; o++) {
                float b0 = sB3[o0 + 2 * o], b1v = sB3[o0 + 2 * o + 1];
                float2 a0 = up2(acc[0][o]), a1 = up2(acc[1][o]);
                float2 a2 = up2(acc[2][o]), a3 = up2(acc[3][o]);
                float me = fmaxf(fmaxf(a0.x, a1.x), fmaxf(a2.x, a3.x));
                float mo = fmaxf(fmaxf(a0.y, a1.y), fmaxf(a2.y, a3.y));
                me = fmaxf(me + b0, 0.0f);
                mo = fmaxf(mo + b1v, 0.0f);
#pragma unroll
                for (int off = 1; off < 8; off <<= 1) {
                    me = fmaxf(me, __shfl_xor_sync(0xffffffffu, me, off));
                    mo = fmaxf(mo, __shfl_xor_sync(0xffffffffu, mo, off));
                }
                if (q == 0) {
                    out_np[((size_t)b * C3n + (o0 + 2 * o)) * Sn + (s0 + sl)]     = me;
                    out_np[((size_t)b * C3n + (o0 + 2 * o + 1)) * Sn + (s0 + sl)] = mo;
                }
            }
        }
    }
}

// ---------------------------------------------------------------------------
extern "C" void kernel_launch(void* const* d_in, const int* in_sizes, int n_in,
                              void* d_out, int out_size)
{
    (void)in_sizes; (void)n_in; (void)out_size;
    const float* xyz = (const float*)d_in[0];
    const float* pts = (const float*)d_in[1];
    const float* W1  = (const float*)d_in[2];
    const float* b1  = (const float*)d_in[3];
    const float* W2  = (const float*)d_in[4];
    const float* b2  = (const float*)d_in[5];
    const float* W3  = (const float*)d_in[6];
    const float* b3  = (const float*)d_in[7];

    float* out      = (float*)d_out;
    float* out_xyz  = out;                       // (B,S,3)
    float* out_np   = out + (size_t)Bn * Sn * 3; // (B,128,S)

    cudaFuncSetAttribute(fps_prep_kernel, cudaFuncAttributeMaxDynamicSharedMemorySize, FPS_SMEM_BYTES);
    cudaFuncSetAttribute(knn_kernel, cudaFuncAttributeMaxDynamicSharedMemorySize, Nn * 16);
    cudaFuncSetAttribute(mlp_kernel, cudaFuncAttributeMaxDynamicSharedMemorySize, MLP_SMEM_BYTES);

    fps_prep_kernel<<<16 + 128, 512, FPS_SMEM_BYTES>>>(xyz, pts, out_xyz);
    knn_kernel<<<dim3(Sn / 64, Bn), 256, Nn * 16>>>(xyz, out_xyz);
    mlp_kernel<<<dim3(Sn / 8, Bn), 256, MLP_SMEM_BYTES>>>(xyz, W1, b1, W2, b2, W3, b3, out_np);
}

// round 7
// speedup vs baseline: 2.5106x; 1.3462x over previous
#include <cuda_runtime.h>

// Problem constants (fixed shapes per problem spec)
namespace {
constexpr int Bn  = 16;
constexpr int Nn  = 4096;
constexpr int Sn  = 1024;
constexpr int CPn = 64;   // point feature channels
constexpr int C3n = 128;  // final MLP out channels
constexpr int NBLK = 144; // 16 fps blocks + 128 worker blocks (<= 148 SMs)
}

// Persistent device scratch (no allocation). All sync counters are MONOTONE
// across launches/replays (never reset), so graph replay and ncu replay stay
// correct without initialization.
__device__ float    g_ptsT[(size_t)Bn * Nn * CPn];  // points (B,N,CP)
__device__ float4   g_spG[Bn * Nn];                 // (x,y,z,|p|^2) per point
__device__ unsigned g_bar;                          // ticket barrier
__device__ unsigned g_progress[Bn];                 // fps centroids produced
__device__ unsigned g_tcount[Bn];                   // worker prologues done

// ---------------------------------------------------------------------------
// helpers
// ---------------------------------------------------------------------------
__device__ __forceinline__ unsigned long long pk2(float lo, float hi) {
    unsigned long long r;
    asm("mov.b64 %0, {%1, %2};" : "=l"(r) : "f"(lo), "f"(hi));
    return r;
}
__device__ __forceinline__ void fma2(unsigned long long& d,
                                     unsigned long long a, unsigned long long b) {
    asm("fma.rn.f32x2 %0, %1, %2, %0;" : "+l"(d) : "l"(a), "l"(b));
}
__device__ __forceinline__ unsigned long long fma2v(unsigned long long a,
                                                    unsigned long long b,
                                                    unsigned long long c) {
    unsigned long long d;
    asm("fma.rn.f32x2 %0, %1, %2, %3;" : "=l"(d) : "l"(a), "l"(b), "l"(c));
    return d;
}
__device__ __forceinline__ unsigned long long mul2(unsigned long long a,
                                                   unsigned long long b) {
    unsigned long long d;
    asm("mul.rn.f32x2 %0, %1, %2;" : "=l"(d) : "l"(a), "l"(b));
    return d;
}
__device__ __forceinline__ unsigned long long add2(unsigned long long a,
                                                   unsigned long long b) {
    unsigned long long d;
    asm("add.rn.f32x2 %0, %1, %2;" : "=l"(d) : "l"(a), "l"(b));
    return d;
}
__device__ __forceinline__ float2 up2(unsigned long long v) {
    float lo, hi;
    asm("mov.b64 {%0, %1}, %2;" : "=f"(lo), "=f"(hi) : "l"(v));
    return make_float2(lo, hi);
}
__device__ __forceinline__ unsigned acq_u32(const unsigned* p) {
    unsigned v;
    asm volatile("ld.global.acquire.gpu.u32 %0, [%1];" : "=r"(v) : "l"(p));
    return v;
}
__device__ __forceinline__ void rel_u32(unsigned* p, unsigned v) {
    asm volatile("st.global.release.gpu.u32 [%0], %1;" :: "l"(p), "r"(v) : "memory");
}
__device__ __forceinline__ float ldcg_f(const float* p) {
    float v;
    asm volatile("ld.global.cg.f32 %0, [%1];" : "=f"(v) : "l"(p));
    return v;
}

// ---------------------------------------------------------------------------
// Worker SMEM layout (floats):
//   W1t[67][64] W2t[64][64] W3t[64][128] b1 b2 b3 | knn idx (512 ints) |
//   Xt[67][ST]  H1[64][ST]   (H2 aliases Xt; transpose tile aliases Xt)
// ---------------------------------------------------------------------------
constexpr int ST       = 260;
constexpr int OFF_W1T  = 0;
constexpr int OFF_W2T  = OFF_W1T + 67 * 64;
constexpr int OFF_W3T  = OFF_W2T + 64 * 64;
constexpr int OFF_B1   = OFF_W3T + 64 * 128;
constexpr int OFF_B2   = OFF_B1 + 64;
constexpr int OFF_B3   = OFF_B2 + 64;
constexpr int OFF_KNN  = OFF_B3 + 128;          // 512 ints
constexpr int OFF_XT   = OFF_KNN + 512;
constexpr int OFF_H1   = OFF_XT + 67 * ST;
constexpr int SMEM_FLOATS = OFF_H1 + 64 * ST;
constexpr int SMEM_BYTES  = SMEM_FLOATS * 4;    // 205,616 B

// One dense layer tile for 512 threads: 4 points x 8 outs per thread.
template <int C, int WS>
__device__ __forceinline__ void layer8(const float* __restrict__ Xs,
                                       const float* __restrict__ Wt,
                                       const float* __restrict__ Bs,
                                       float* __restrict__ Hs,
                                       int p0, int o0)
{
    unsigned long long acc[4][4];
#pragma unroll
    for (int i = 0; i < 4; i++)
#pragma unroll
        for (int o = 0; o < 4; o++) acc[i][o] = pk2(0.0f, 0.0f);

    for (int c = 0; c < C; c++) {
        float4 xv = *(const float4*)(Xs + c * ST + p0);
        const ulonglong2* wp = (const ulonglong2*)(Wt + c * WS + o0);
        ulonglong2 wa = wp[0], wb = wp[1];
        unsigned long long xq[4] = {pk2(xv.x, xv.x), pk2(xv.y, xv.y),
                                    pk2(xv.z, xv.z), pk2(xv.w, xv.w)};
        unsigned long long wq[4] = {wa.x, wa.y, wb.x, wb.y};
#pragma unroll
        for (int i = 0; i < 4; i++)
#pragma unroll
            for (int o = 0; o < 4; o++) fma2(acc[i][o], xq[i], wq[o]);
    }
#pragma unroll
    for (int o = 0; o < 4; o++) {
        float b0 = Bs[o0 + 2 * o], b1 = Bs[o0 + 2 * o + 1];
        float2 a0 = up2(acc[0][o]), a1 = up2(acc[1][o]);
        float2 a2 = up2(acc[2][o]), a3 = up2(acc[3][o]);
        float4 ve = make_float4(fmaxf(a0.x + b0, 0.f), fmaxf(a1.x + b0, 0.f),
                                fmaxf(a2.x + b0, 0.f), fmaxf(a3.x + b0, 0.f));
        float4 vo = make_float4(fmaxf(a0.y + b1, 0.f), fmaxf(a1.y + b1, 0.f),
                                fmaxf(a2.y + b1, 0.f), fmaxf(a3.y + b1, 0.f));
        *(float4*)(Hs + (o0 + 2 * o) * ST + p0)     = ve;
        *(float4*)(Hs + (o0 + 2 * o + 1) * ST + p0) = vo;
    }
}

// ---------------------------------------------------------------------------
// The megakernel: blocks 0..15 = FPS producers, 16..143 = knn+mlp workers.
// ---------------------------------------------------------------------------
__global__ __launch_bounds__(512) void sa_kernel(
    const float* __restrict__ xyz, const float* __restrict__ pts,
    const float* __restrict__ W1, const float* __restrict__ b1,
    const float* __restrict__ W2, const float* __restrict__ b2,
    const float* __restrict__ W3, const float* __restrict__ b3,
    float* out_xyz, float* out_np)
{
    extern __shared__ float sm[];
    int bx = blockIdx.x;
    int tid = threadIdx.x;
    const unsigned FULL = 0xffffffffu;

    __shared__ unsigned s_base[2];

    // read monotone bases BEFORE the rendezvous (no producer has incremented
    // in this launch yet), then ticket barrier over all 144 co-resident blocks
    if (tid == 0) {
        int bb = (bx < 16) ? bx : ((bx - 16) >> 3);
        s_base[0] = acq_u32(&g_progress[bb]);
        s_base[1] = acq_u32(&g_tcount[bb]);
        unsigned ticket = atomicAdd(&g_bar, 1u);
        unsigned gen = ticket / NBLK;
        while (acq_u32(&g_bar) < (gen + 1) * NBLK) __nanosleep(64);
    }
    __syncthreads();
    unsigned pbase = s_base[0];

    if (bx < 16) {
        // =================== FPS producer (identical math to R6) ===========
        float* sx = sm;
        float* sy = sm + Nn;
        float* sz = sm + 2 * Nn;
        unsigned* sdist = (unsigned*)(sm + 3 * Nn);
        unsigned* sidx  = sdist + 32;

        int b = bx, t = tid;
        const float* xb = xyz + (size_t)b * Nn * 3;

        unsigned long long px2[4], py2[4], pz2[4];
        float dist[8];
#pragma unroll
        for (int i = 0; i < 4; i++) {
            int j0 = t + (2 * i) * 512;
            int j1 = t + (2 * i + 1) * 512;
            float x0 = xb[3 * j0], y0 = xb[3 * j0 + 1], z0 = xb[3 * j0 + 2];
            float x1 = xb[3 * j1], y1 = xb[3 * j1 + 1], z1 = xb[3 * j1 + 2];
            px2[i] = pk2(x0, x1); py2[i] = pk2(y0, y1); pz2[i] = pk2(z0, z1);
            sx[j0] = x0; sy[j0] = y0; sz[j0] = z0;
            sx[j1] = x1; sy[j1] = y1; sz[j1] = z1;
            dist[2 * i] = 1e10f; dist[2 * i + 1] = 1e10f;
        }
        __syncthreads();

        float cx = sx[0], cy = sy[0], cz = sz[0];
        if (t == 0) {
            float* o = out_xyz + (size_t)b * Sn * 3;
            o[0] = cx; o[1] = cy; o[2] = cz;
            rel_u32(&g_progress[b], pbase + 1u);
        }

        int lane = t & 31, wd = t >> 5;
        for (int it = 1; it < Sn; ++it) {
            unsigned long long ncx2 = pk2(-cx, -cx);
            unsigned long long ncy2 = pk2(-cy, -cy);
            unsigned long long ncz2 = pk2(-cz, -cz);
#pragma unroll
            for (int i = 0; i < 4; i++) {
                unsigned long long dx = add2(px2[i], ncx2);
                unsigned long long dy = add2(py2[i], ncy2);
                unsigned long long dz = add2(pz2[i], ncz2);
                unsigned long long d2 = mul2(dx, dx);
                d2 = fma2v(dy, dy, d2);
                d2 = fma2v(dz, dz, d2);
                float2 dd = up2(d2);
                dist[2 * i]     = fminf(dist[2 * i], dd.x);
                dist[2 * i + 1] = fminf(dist[2 * i + 1], dd.y);
            }
            float mv = fmaxf(fmaxf(fmaxf(dist[0], dist[1]), fmaxf(dist[2], dist[3])),
                             fmaxf(fmaxf(dist[4], dist[5]), fmaxf(dist[6], dist[7])));
            int mi = t;
#pragma unroll
            for (int s = 7; s >= 0; s--)
                if (dist[s] == mv) mi = t + s * 512;   // lowest index wins

            unsigned db = __float_as_uint(mv);
            unsigned wm = __reduce_max_sync(FULL, db);
            unsigned ci = (db == wm) ? (unsigned)mi : 0xffffffffu;
            unsigned wi = __reduce_min_sync(FULL, ci);
            int slot = (it & 1) * 16 + wd;
            if (lane == 0) { sdist[slot] = wm; sidx[slot] = wi; }
            __syncthreads();

            int rs = (it & 1) * 16 + (lane & 15);
            unsigned d16 = sdist[rs];
            unsigned i16 = sidx[rs];
            unsigned gm  = __reduce_max_sync(FULL, d16);
            unsigned gc  = (d16 == gm) ? i16 : 0xffffffffu;
            unsigned far = __reduce_min_sync(FULL, gc);
            cx = sx[far]; cy = sy[far]; cz = sz[far];
            if (t == 0) {
                float* o = out_xyz + ((size_t)b * Sn + it) * 3;
                o[0] = cx; o[1] = cy; o[2] = cz;
                rel_u32(&g_progress[b], pbase + (unsigned)it + 1u);
            }
        }
        return;
    }

    // ======================= worker: knn + gather + MLP ====================
    int b  = (bx - 16) >> 3;
    int wl = (bx - 16) & 7;
    unsigned tbase = s_base[1];

    float* sW1t = sm + OFF_W1T;
    float* sW2t = sm + OFF_W2T;
    float* sW3t = sm + OFF_W3T;
    float* sB1  = sm + OFF_B1;
    float* sB2  = sm + OFF_B2;
    float* sB3  = sm + OFF_B3;
    int*   sknn = (int*)(sm + OFF_KNN);
    float* sXt  = sm + OFF_XT;
    float* sH1  = sm + OFF_H1;
    float* sH2  = sXt;

    // --- prologue: weights to smem ---
    for (int i = tid; i < 64 * 67; i += 512) { int o = i / 67, c = i % 67; sW1t[c * 64 + o] = W1[i]; }
    for (int i = tid; i < 64 * 64; i += 512) { int o = i >> 6, c = i & 63; sW2t[c * 64 + o] = W2[i]; }
    for (int i = tid; i < 128 * 64; i += 512){ int o = i >> 6, c = i & 63; sW3t[c * 128 + o] = W3[i]; }
    if (tid < 64)  sB1[tid] = b1[tid];
    if (tid < 64)  sB2[tid] = b2[tid];
    if (tid < 128) sB3[tid] = b3[tid];

    // --- prologue: transpose this worker's slice (512 n-columns) ---
    {
        float (*tile)[33] = (float (*)[33])(sm + OFF_XT);
        int n0 = wl * 512;
        int txx = tid & 31, tyy = tid >> 5;   // tyy 0..15
        const float* src = pts + (size_t)b * CPn * Nn;
        float* dst = g_ptsT + (size_t)b * Nn * CPn;
        for (int ct = 0; ct < 2; ct++) {
            int c0 = ct * 32;
            for (int nt = 0; nt < 16; nt++) {
                int nn0 = n0 + nt * 32;
                tile[tyy][txx]      = src[(size_t)(c0 + tyy) * Nn + nn0 + txx];
                tile[tyy + 16][txx] = src[(size_t)(c0 + tyy + 16) * Nn + nn0 + txx];
                __syncthreads();
                dst[(size_t)(nn0 + tyy) * CPn + c0 + txx]      = tile[txx][tyy];
                dst[(size_t)(nn0 + tyy + 16) * CPn + c0 + txx] = tile[txx][tyy + 16];
                __syncthreads();
            }
        }
    }
    // --- prologue: candidate table slice (x,y,z,|p|^2) ---
    {
        int j = wl * 512 + tid;
        const float* xb = xyz + (size_t)b * Nn * 3;
        float x = xb[3 * j], y = xb[3 * j + 1], z = xb[3 * j + 2];
        g_spG[b * Nn + j] = make_float4(x, y, z, fmaf(z, z, fmaf(y, y, x * x)));
    }
    __threadfence();
    __syncthreads();
    if (tid == 0) {
        atomicAdd(&g_tcount[b], 1u);
        while (acq_u32(&g_tcount[b]) < tbase + 8u) __nanosleep(128);
    }
    __syncthreads();

    int wid = tid >> 5, lane = tid & 31;
    const float INF = __int_as_float(0x7f800000);
    const float4* spb = g_spG + b * Nn;

    for (int k = 0; k < 8; k++) {
        int chunk = wl + 8 * k;          // increasing centroid order per worker
        int s0 = chunk * 16;
        if (tid == 0) {
            while (acq_u32(&g_progress[b]) < pbase + (unsigned)(s0 + 16)) __nanosleep(128);
        }
        __syncthreads();

        // ---- knn: warp wid -> centroid s0+wid (warp-collective top-32) ----
        {
            int s = s0 + wid;
            const float* cp = out_xyz + ((size_t)b * Sn + s) * 3;
            float nx = ldcg_f(cp), ny = ldcg_f(cp + 1), nz = ldcg_f(cp + 2);
            float cn = fmaf(nz, nz, fmaf(ny, ny, nx * nx));
            float cur_d = INF; int cur_i = 0x7fffffff;
            float wmax = INF;
            for (int j0 = 0; j0 < Nn; j0 += 32) {
                float4 p = spb[j0 + lane];
                float dot = fmaf(nz, p.z, fmaf(ny, p.y, nx * p.x));
                float d = (cn + p.w) - 2.0f * dot;
                unsigned mask = __ballot_sync(FULL, d <= wmax);
                while (mask) {
                    int src = __ffs(mask) - 1;
                    mask &= mask - 1;
                    float dn = __shfl_sync(FULL, d, src);
                    int   ix = j0 + src;
                    bool less = (cur_d < dn) || (cur_d == dn && cur_i < ix);
                    int pos = __popc(__ballot_sync(FULL, less));
                    if (pos < 32) {
                        float ud = __shfl_up_sync(FULL, cur_d, 1);
                        int   ui = __shfl_up_sync(FULL, cur_i, 1);
                        if (lane > pos)       { cur_d = ud; cur_i = ui; }
                        else if (lane == pos) { cur_d = dn; cur_i = ix; }
                        wmax = __shfl_sync(FULL, cur_d, 31);
                    }
                }
            }
            sknn[wid * 32 + lane] = cur_i;
        }
        __syncthreads();

        // ---- two 8-centroid MLP sub-tiles ----
        for (int sub = 0; sub < 2; sub++) {
            for (int p = wid; p < 256; p += 16) {
                int sl = sub * 8 + (p >> 5);
                int j = sknn[sl * 32 + (p & 31)];
                const float* pr = g_ptsT + ((size_t)(b * Nn + j)) * CPn;
                float v0 = (lane < 3) ? xyz[((size_t)(b * Nn + j)) * 3 + lane] : pr[lane - 3];
                sXt[lane * ST + p]        = v0;
                sXt[(lane + 32) * ST + p] = pr[lane + 29];
                if (lane < 3) sXt[(lane + 64) * ST + p] = pr[lane + 61];
            }
            __syncthreads();

            int tx = tid & 63, ty = tid >> 6;
            int p0 = tx * 4;
            layer8<67, 64>(sXt, sW1t, sB1, sH1, p0, ty * 8);
            __syncthreads();
            layer8<64, 64>(sH1, sW2t, sB2, sH2, p0, ty * 8);
            __syncthreads();

            // layer 3: 64 -> 128 + maxpool over k
            {
                int q  = tx & 7;
                int sl = tx >> 3;
                for (int pass = 0; pass < 2; pass++) {
                    int o0 = ty * 8 + pass * 64;
                    unsigned long long acc[4][4];
#pragma unroll
                    for (int i = 0; i < 4; i++)
#pragma unroll
                        for (int o = 0; o < 4; o++) acc[i][o] = pk2(0.0f, 0.0f);
                    for (int c = 0; c < 64; c++) {
                        float4 xv = *(const float4*)(sH2 + c * ST + p0);
                        const ulonglong2* wp = (const ulonglong2*)(sW3t + c * 128 + o0);
                        ulonglong2 wa = wp[0], wb = wp[1];
                        unsigned long long xq[4] = {pk2(xv.x, xv.x), pk2(xv.y, xv.y),
                                                    pk2(xv.z, xv.z), pk2(xv.w, xv.w)};
                        unsigned long long wq[4] = {wa.x, wa.y, wb.x, wb.y};
#pragma unroll
                        for (int i = 0; i < 4; i++)
#pragma unroll
                            for (int o = 0; o < 4; o++) fma2(acc[i][o], xq[i], wq[o]);
                    }
#pragma unroll
                    for (int o = 0; o < 4; o++) {
                        float b0 = sB3[o0 + 2 * o], b1v = sB3[o0 + 2 * o + 1];
                        float2 a0 = up2(acc[0][o]), a1 = up2(acc[1][o]);
                        float2 a2 = up2(acc[2][o]), a3 = up2(acc[3][o]);
                        float me = fmaxf(fmaxf(a0.x, a1.x), fmaxf(a2.x, a3.x));
                        float mo = fmaxf(fmaxf(a0.y, a1.y), fmaxf(a2.y, a3.y));
                        me = fmaxf(me + b0, 0.0f);
                        mo = fmaxf(mo + b1v, 0.0f);
#pragma unroll
                        for (int off = 1; off < 8; off <<= 1) {
                            me = fmaxf(me, __shfl_xor_sync(FULL, me, off));
                            mo = fmaxf(mo, __shfl_xor_sync(FULL, mo, off));
                        }
                        if (q == 0) {
                            int sg = s0 + sub * 8 + sl;
                            out_np[((size_t)b * C3n + (o0 + 2 * o)) * Sn + sg]     = me;
                            out_np[((size_t)b * C3n + (o0 + 2 * o + 1)) * Sn + sg] = mo;
                        }
                    }
                }
            }
            __syncthreads();
        }
    }
}

// ---------------------------------------------------------------------------
extern "C" void kernel_launch(void* const* d_in, const int* in_sizes, int n_in,
                              void* d_out, int out_size)
{
    (void)in_sizes; (void)n_in; (void)out_size;
    const float* xyz = (const float*)d_in[0];
    const float* pts = (const float*)d_in[1];
    const float* W1  = (const float*)d_in[2];
    const float* b1  = (const float*)d_in[3];
    const float* W2  = (const float*)d_in[4];
    const float* b2  = (const float*)d_in[5];
    const float* W3  = (const float*)d_in[6];
    const float* b3  = (const float*)d_in[7];

    float* out      = (float*)d_out;
    float* out_xyz  = out;                       // (B,S,3)
    float* out_np   = out + (size_t)Bn * Sn * 3; // (B,128,S)

    cudaFuncSetAttribute(sa_kernel, cudaFuncAttributeMaxDynamicSharedMemorySize, SMEM_BYTES);
    sa_kernel<<<NBLK, 512, SMEM_BYTES>>>(xyz, pts, W1, b1, W2, b2, W3, b3,
                                         out_xyz, out_np);
}

// round 8
// speedup vs baseline: 2.7499x; 1.0953x over previous
#include <cuda_runtime.h>

// Problem constants (fixed shapes per problem spec)
namespace {
constexpr int Bn  = 16;
constexpr int Nn  = 4096;
constexpr int Sn  = 1024;
constexpr int CPn = 64;   // point feature channels
constexpr int C3n = 128;  // final MLP out channels
constexpr int NBLK = 144; // 16 fps blocks + 128 worker blocks (<= 148 SMs)
}

// Persistent device scratch (no allocation). All sync counters are MONOTONE
// across launches/replays (never reset), so graph replay and ncu replay stay
// correct without initialization.
__device__ float    g_ptsT[(size_t)Bn * Nn * CPn];  // points (B,N,CP)
__device__ float4   g_spG[Bn * Nn];                 // (x,y,z,|p|^2) per point
__device__ unsigned g_bar;                          // ticket barrier
__device__ unsigned g_progress[Bn];                 // fps centroids produced
__device__ unsigned g_tcount[Bn];                   // worker prologues done

// ---------------------------------------------------------------------------
// helpers
// ---------------------------------------------------------------------------
__device__ __forceinline__ unsigned long long pk2(float lo, float hi) {
    unsigned long long r;
    asm("mov.b64 %0, {%1, %2};" : "=l"(r) : "f"(lo), "f"(hi));
    return r;
}
__device__ __forceinline__ void fma2(unsigned long long& d,
                                     unsigned long long a, unsigned long long b) {
    asm("fma.rn.f32x2 %0, %1, %2, %0;" : "+l"(d) : "l"(a), "l"(b));
}
__device__ __forceinline__ unsigned long long fma2v(unsigned long long a,
                                                    unsigned long long b,
                                                    unsigned long long c) {
    unsigned long long d;
    asm("fma.rn.f32x2 %0, %1, %2, %3;" : "=l"(d) : "l"(a), "l"(b), "l"(c));
    return d;
}
__device__ __forceinline__ unsigned long long mul2(unsigned long long a,
                                                   unsigned long long b) {
    unsigned long long d;
    asm("mul.rn.f32x2 %0, %1, %2;" : "=l"(d) : "l"(a), "l"(b));
    return d;
}
__device__ __forceinline__ unsigned long long add2(unsigned long long a,
                                                   unsigned long long b) {
    unsigned long long d;
    asm("add.rn.f32x2 %0, %1, %2;" : "=l"(d) : "l"(a), "l"(b));
    return d;
}
__device__ __forceinline__ float2 up2(unsigned long long v) {
    float lo, hi;
    asm("mov.b64 {%0, %1}, %2;" : "=f"(lo), "=f"(hi) : "l"(v));
    return make_float2(lo, hi);
}
__device__ __forceinline__ unsigned acq_u32(const unsigned* p) {
    unsigned v;
    asm volatile("ld.global.acquire.gpu.u32 %0, [%1];" : "=r"(v) : "l"(p));
    return v;
}
__device__ __forceinline__ void rel_u32(unsigned* p, unsigned v) {
    asm volatile("st.global.release.gpu.u32 [%0], %1;" :: "l"(p), "r"(v) : "memory");
}
__device__ __forceinline__ float ldcg_f(const float* p) {
    float v;
    asm volatile("ld.global.cg.f32 %0, [%1];" : "=f"(v) : "l"(p));
    return v;
}

// ---------------------------------------------------------------------------
// Worker SMEM layout (floats):
//   W1t[67][64] W2t[64][64] W3t[64][128] b1 b2 b3 | knn idx (512 ints) |
//   Xt[67][ST]  H1[64][ST]
// H1 doubles as the staged kNN candidate table (4096 float4 = 65536 floats
// <= 64*ST = 66560) at the start of each chunk; H1 is dead between chunks.
// ---------------------------------------------------------------------------
constexpr int ST       = 260;
constexpr int OFF_W1T  = 0;
constexpr int OFF_W2T  = OFF_W1T + 67 * 64;
constexpr int OFF_W3T  = OFF_W2T + 64 * 64;
constexpr int OFF_B1   = OFF_W3T + 64 * 128;
constexpr int OFF_B2   = OFF_B1 + 64;
constexpr int OFF_B3   = OFF_B2 + 64;
constexpr int OFF_KNN  = OFF_B3 + 128;          // 512 ints
constexpr int OFF_XT   = OFF_KNN + 512;
constexpr int OFF_H1   = OFF_XT + 67 * ST;      // 16B-aligned (34764 % 4 == 0)
constexpr int SMEM_FLOATS = OFF_H1 + 64 * ST;
constexpr int SMEM_BYTES  = SMEM_FLOATS * 4;    // 205,616 B

// One dense layer tile for 512 threads: 4 points x 8 outs per thread.
template <int C, int WS>
__device__ __forceinline__ void layer8(const float* __restrict__ Xs,
                                       const float* __restrict__ Wt,
                                       const float* __restrict__ Bs,
                                       float* __restrict__ Hs,
                                       int p0, int o0)
{
    unsigned long long acc[4][4];
#pragma unroll
    for (int i = 0; i < 4; i++)
#pragma unroll
        for (int o = 0; o < 4; o++) acc[i][o] = pk2(0.0f, 0.0f);

    for (int c = 0; c < C; c++) {
        float4 xv = *(const float4*)(Xs + c * ST + p0);
        const ulonglong2* wp = (const ulonglong2*)(Wt + c * WS + o0);
        ulonglong2 wa = wp[0], wb = wp[1];
        unsigned long long xq[4] = {pk2(xv.x, xv.x), pk2(xv.y, xv.y),
                                    pk2(xv.z, xv.z), pk2(xv.w, xv.w)};
        unsigned long long wq[4] = {wa.x, wa.y, wb.x, wb.y};
#pragma unroll
        for (int i = 0; i < 4; i++)
#pragma unroll
            for (int o = 0; o < 4; o++) fma2(acc[i][o], xq[i], wq[o]);
    }
#pragma unroll
    for (int o = 0; o < 4; o++) {
        float b0 = Bs[o0 + 2 * o], b1 = Bs[o0 + 2 * o + 1];
        float2 a0 = up2(acc[0][o]), a1 = up2(acc[1][o]);
        float2 a2 = up2(acc[2][o]), a3 = up2(acc[3][o]);
        float4 ve = make_float4(fmaxf(a0.x + b0, 0.f), fmaxf(a1.x + b0, 0.f),
                                fmaxf(a2.x + b0, 0.f), fmaxf(a3.x + b0, 0.f));
        float4 vo = make_float4(fmaxf(a0.y + b1, 0.f), fmaxf(a1.y + b1, 0.f),
                                fmaxf(a2.y + b1, 0.f), fmaxf(a3.y + b1, 0.f));
        *(float4*)(Hs + (o0 + 2 * o) * ST + p0)     = ve;
        *(float4*)(Hs + (o0 + 2 * o + 1) * ST + p0) = vo;
    }
}

// ---------------------------------------------------------------------------
// The megakernel: blocks 0..15 = FPS producers, 16..143 = knn+mlp workers.
// ---------------------------------------------------------------------------
__global__ __launch_bounds__(512) void sa_kernel(
    const float* __restrict__ xyz, const float* __restrict__ pts,
    const float* __restrict__ W1, const float* __restrict__ b1,
    const float* __restrict__ W2, const float* __restrict__ b2,
    const float* __restrict__ W3, const float* __restrict__ b3,
    float* out_xyz, float* out_np)
{
    extern __shared__ float sm[];
    int bx = blockIdx.x;
    int tid = threadIdx.x;
    const unsigned FULL = 0xffffffffu;

    __shared__ unsigned s_base[2];

    // read monotone bases BEFORE the rendezvous (no producer has incremented
    // in this launch yet), then ticket barrier over all 144 co-resident blocks
    if (tid == 0) {
        int bb = (bx < 16) ? bx : ((bx - 16) >> 3);
        s_base[0] = acq_u32(&g_progress[bb]);
        s_base[1] = acq_u32(&g_tcount[bb]);
        unsigned ticket = atomicAdd(&g_bar, 1u);
        unsigned gen = ticket / NBLK;
        while (acq_u32(&g_bar) < (gen + 1) * NBLK) __nanosleep(64);
    }
    __syncthreads();
    unsigned pbase = s_base[0];

    if (bx < 16) {
        // =================== FPS producer (identical math to R6/R7) ========
        float* sx = sm;
        float* sy = sm + Nn;
        float* sz = sm + 2 * Nn;
        unsigned* sdist = (unsigned*)(sm + 3 * Nn);
        unsigned* sidx  = sdist + 32;

        int b = bx, t = tid;
        const float* xb = xyz + (size_t)b * Nn * 3;

        unsigned long long px2[4], py2[4], pz2[4];
        float dist[8];
#pragma unroll
        for (int i = 0; i < 4; i++) {
            int j0 = t + (2 * i) * 512;
            int j1 = t + (2 * i + 1) * 512;
            float x0 = xb[3 * j0], y0 = xb[3 * j0 + 1], z0 = xb[3 * j0 + 2];
            float x1 = xb[3 * j1], y1 = xb[3 * j1 + 1], z1 = xb[3 * j1 + 2];
            px2[i] = pk2(x0, x1); py2[i] = pk2(y0, y1); pz2[i] = pk2(z0, z1);
            sx[j0] = x0; sy[j0] = y0; sz[j0] = z0;
            sx[j1] = x1; sy[j1] = y1; sz[j1] = z1;
            dist[2 * i] = 1e10f; dist[2 * i + 1] = 1e10f;
        }
        __syncthreads();

        float cx = sx[0], cy = sy[0], cz = sz[0];
        if (t == 0) {
            float* o = out_xyz + (size_t)b * Sn * 3;
            o[0] = cx; o[1] = cy; o[2] = cz;
            rel_u32(&g_progress[b], pbase + 1u);
        }

        int lane = t & 31, wd = t >> 5;
        for (int it = 1; it < Sn; ++it) {
            unsigned long long ncx2 = pk2(-cx, -cx);
            unsigned long long ncy2 = pk2(-cy, -cy);
            unsigned long long ncz2 = pk2(-cz, -cz);
#pragma unroll
            for (int i = 0; i < 4; i++) {
                unsigned long long dx = add2(px2[i], ncx2);
                unsigned long long dy = add2(py2[i], ncy2);
                unsigned long long dz = add2(pz2[i], ncz2);
                unsigned long long d2 = mul2(dx, dx);
                d2 = fma2v(dy, dy, d2);
                d2 = fma2v(dz, dz, d2);
                float2 dd = up2(d2);
                dist[2 * i]     = fminf(dist[2 * i], dd.x);
                dist[2 * i + 1] = fminf(dist[2 * i + 1], dd.y);
            }
            float mv = fmaxf(fmaxf(fmaxf(dist[0], dist[1]), fmaxf(dist[2], dist[3])),
                             fmaxf(fmaxf(dist[4], dist[5]), fmaxf(dist[6], dist[7])));
            int mi = t;
#pragma unroll
            for (int s = 7; s >= 0; s--)
                if (dist[s] == mv) mi = t + s * 512;   // lowest index wins

            unsigned db = __float_as_uint(mv);
            unsigned wm = __reduce_max_sync(FULL, db);
            unsigned ci = (db == wm) ? (unsigned)mi : 0xffffffffu;
            unsigned wi = __reduce_min_sync(FULL, ci);
            int slot = (it & 1) * 16 + wd;
            if (lane == 0) { sdist[slot] = wm; sidx[slot] = wi; }
            __syncthreads();

            int rs = (it & 1) * 16 + (lane & 15);
            unsigned d16 = sdist[rs];
            unsigned i16 = sidx[rs];
            unsigned gm  = __reduce_max_sync(FULL, d16);
            unsigned gc  = (d16 == gm) ? i16 : 0xffffffffu;
            unsigned far = __reduce_min_sync(FULL, gc);
            cx = sx[far]; cy = sy[far]; cz = sz[far];
            if (t == 0) {
                float* o = out_xyz + ((size_t)b * Sn + it) * 3;
                o[0] = cx; o[1] = cy; o[2] = cz;
                rel_u32(&g_progress[b], pbase + (unsigned)it + 1u);
            }
        }
        return;
    }

    // ======================= worker: knn + gather + MLP ====================
    int b  = (bx - 16) >> 3;
    int wl = (bx - 16) & 7;
    unsigned tbase = s_base[1];

    float* sW1t = sm + OFF_W1T;
    float* sW2t = sm + OFF_W2T;
    float* sW3t = sm + OFF_W3T;
    float* sB1  = sm + OFF_B1;
    float* sB2  = sm + OFF_B2;
    float* sB3  = sm + OFF_B3;
    int*   sknn = (int*)(sm + OFF_KNN);
    float* sXt  = sm + OFF_XT;
    float* sH1  = sm + OFF_H1;
    float* sH2  = sXt;
    float4* spS = (float4*)(sm + OFF_H1);   // staged candidate table (aliases H1)

    // --- prologue: weights to smem ---
    for (int i = tid; i < 64 * 67; i += 512) { int o = i / 67, c = i % 67; sW1t[c * 64 + o] = W1[i]; }
    for (int i = tid; i < 64 * 64; i += 512) { int o = i >> 6, c = i & 63; sW2t[c * 64 + o] = W2[i]; }
    for (int i = tid; i < 128 * 64; i += 512){ int o = i >> 6, c = i & 63; sW3t[c * 128 + o] = W3[i]; }
    if (tid < 64)  sB1[tid] = b1[tid];
    if (tid < 64)  sB2[tid] = b2[tid];
    if (tid < 128) sB3[tid] = b3[tid];

    // --- prologue: transpose this worker's slice (512 n-columns) ---
    {
        float (*tile)[33] = (float (*)[33])(sm + OFF_XT);
        int n0 = wl * 512;
        int txx = tid & 31, tyy = tid >> 5;   // tyy 0..15
        const float* src = pts + (size_t)b * CPn * Nn;
        float* dst = g_ptsT + (size_t)b * Nn * CPn;
        for (int ct = 0; ct < 2; ct++) {
            int c0 = ct * 32;
            for (int nt = 0; nt < 16; nt++) {
                int nn0 = n0 + nt * 32;
                tile[tyy][txx]      = src[(size_t)(c0 + tyy) * Nn + nn0 + txx];
                tile[tyy + 16][txx] = src[(size_t)(c0 + tyy + 16) * Nn + nn0 + txx];
                __syncthreads();
                dst[(size_t)(nn0 + tyy) * CPn + c0 + txx]      = tile[txx][tyy];
                dst[(size_t)(nn0 + tyy + 16) * CPn + c0 + txx] = tile[txx][tyy + 16];
                __syncthreads();
            }
        }
    }
    // --- prologue: candidate table slice (x,y,z,|p|^2) ---
    {
        int j = wl * 512 + tid;
        const float* xb = xyz + (size_t)b * Nn * 3;
        float x = xb[3 * j], y = xb[3 * j + 1], z = xb[3 * j + 2];
        g_spG[b * Nn + j] = make_float4(x, y, z, fmaf(z, z, fmaf(y, y, x * x)));
    }
    __threadfence();
    __syncthreads();
    if (tid == 0) {
        atomicAdd(&g_tcount[b], 1u);
        while (acq_u32(&g_tcount[b]) < tbase + 8u) __nanosleep(128);
    }
    __syncthreads();

    int wid = tid >> 5, lane = tid & 31;
    const float INF = __int_as_float(0x7f800000);
    const float4* spb = g_spG + b * Nn;

    for (int k = 0; k < 8; k++) {
        int chunk = wl + 8 * k;          // increasing centroid order per worker
        int s0 = chunk * 16;

        // stage the candidate table into SMEM (overlaps the progress spin;
        // H1 is dead here — previous chunk's layer2 finished reading it)
#pragma unroll
        for (int i = 0; i < 8; i++) spS[tid + i * 512] = spb[tid + i * 512];

        if (tid == 0) {
            while (acq_u32(&g_progress[b]) < pbase + (unsigned)(s0 + 16)) __nanosleep(128);
        }
        __syncthreads();

        // ---- knn: warp wid -> centroid s0+wid (warp-collective top-32) ----
        {
            int s = s0 + wid;
            const float* cp = out_xyz + ((size_t)b * Sn + s) * 3;
            float nx = ldcg_f(cp), ny = ldcg_f(cp + 1), nz = ldcg_f(cp + 2);
            float cn = fmaf(nz, nz, fmaf(ny, ny, nx * nx));
            float cur_d = INF; int cur_i = 0x7fffffff;
            float wmax = INF;
            for (int j0 = 0; j0 < Nn; j0 += 32) {
                float4 p = spS[j0 + lane];
                float dot = fmaf(nz, p.z, fmaf(ny, p.y, nx * p.x));
                float d = (cn + p.w) - 2.0f * dot;
                unsigned mask = __ballot_sync(FULL, d <= wmax);
                while (mask) {
                    int src = __ffs(mask) - 1;
                    mask &= mask - 1;
                    float dn = __shfl_sync(FULL, d, src);
                    int   ix = j0 + src;
                    bool less = (cur_d < dn) || (cur_d == dn && cur_i < ix);
                    int pos = __popc(__ballot_sync(FULL, less));
                    if (pos < 32) {
                        float ud = __shfl_up_sync(FULL, cur_d, 1);
                        int   ui = __shfl_up_sync(FULL, cur_i, 1);
                        if (lane > pos)       { cur_d = ud; cur_i = ui; }
                        else if (lane == pos) { cur_d = dn; cur_i = ix; }
                        wmax = __shfl_sync(FULL, cur_d, 31);
                    }
                }
            }
            sknn[wid * 32 + lane] = cur_i;
        }
        __syncthreads();

        // ---- two 8-centroid MLP sub-tiles ----
        for (int sub = 0; sub < 2; sub++) {
            for (int p = wid; p < 256; p += 16) {
                int sl = sub * 8 + (p >> 5);
                int j = sknn[sl * 32 + (p & 31)];
                const float* pr = g_ptsT + ((size_t)(b * Nn + j)) * CPn;
                float v0 = (lane < 3) ? xyz[((size_t)(b * Nn + j)) * 3 + lane] : pr[lane - 3];
                sXt[lane * ST + p]        = v0;
                sXt[(lane + 32) * ST + p] = pr[lane + 29];
                if (lane < 3) sXt[(lane + 64) * ST + p] = pr[lane + 61];
            }
            __syncthreads();

            int tx = tid & 63, ty = tid >> 6;
            int p0 = tx * 4;
            layer8<67, 64>(sXt, sW1t, sB1, sH1, p0, ty * 8);
            __syncthreads();
            layer8<64, 64>(sH1, sW2t, sB2, sH2, p0, ty * 8);
            __syncthreads();

            // layer 3: 64 -> 128 + maxpool over k
            {
                int q  = tx & 7;
                int sl = tx >> 3;
                for (int pass = 0; pass < 2; pass++) {
                    int o0 = ty * 8 + pass * 64;
                    unsigned long long acc[4][4];
#pragma unroll
                    for (int i = 0; i < 4; i++)
#pragma unroll
                        for (int o = 0; o < 4; o++) acc[i][o] = pk2(0.0f, 0.0f);
                    for (int c = 0; c < 64; c++) {
                        float4 xv = *(const float4*)(sH2 + c * ST + p0);
                        const ulonglong2* wp = (const ulonglong2*)(sW3t + c * 128 + o0);
                        ulonglong2 wa = wp[0], wb = wp[1];
                        unsigned long long xq[4] = {pk2(xv.x, xv.x), pk2(xv.y, xv.y),
                                                    pk2(xv.z, xv.z), pk2(xv.w, xv.w)};
                        unsigned long long wq[4] = {wa.x, wa.y, wb.x, wb.y};
#pragma unroll
                        for (int i = 0; i < 4; i++)
#pragma unroll
                            for (int o = 0; o < 4; o++) fma2(acc[i][o], xq[i], wq[o]);
                    }
#pragma unroll
                    for (int o = 0; o < 4; o++) {
                        float b0 = sB3[o0 + 2 * o], b1v = sB3[o0 + 2 * o + 1];
                        float2 a0 = up2(acc[0][o]), a1 = up2(acc[1][o]);
                        float2 a2 = up2(acc[2][o]), a3 = up2(acc[3][o]);
                        float me = fmaxf(fmaxf(a0.x, a1.x), fmaxf(a2.x, a3.x));
                        float mo = fmaxf(fmaxf(a0.y, a1.y), fmaxf(a2.y, a3.y));
                        me = fmaxf(me + b0, 0.0f);
                        mo = fmaxf(mo + b1v, 0.0f);
#pragma unroll
                        for (int off = 1; off < 8; off <<= 1) {
                            me = fmaxf(me, __shfl_xor_sync(FULL, me, off));
                            mo = fmaxf(mo, __shfl_xor_sync(FULL, mo, off));
                        }
                        if (q == 0) {
                            int sg = s0 + sub * 8 + sl;
                            out_np[((size_t)b * C3n + (o0 + 2 * o)) * Sn + sg]     = me;
                            out_np[((size_t)b * C3n + (o0 + 2 * o + 1)) * Sn + sg] = mo;
                        }
                    }
                }
            }
            __syncthreads();
        }
    }
}

// ---------------------------------------------------------------------------
extern "C" void kernel_launch(void* const* d_in, const int* in_sizes, int n_in,
                              void* d_out, int out_size)
{
    (void)in_sizes; (void)n_in; (void)out_size;
    const float* xyz = (const float*)d_in[0];
    const float* pts = (const float*)d_in[1];
    const float* W1  = (const float*)d_in[2];
    const float* b1  = (const float*)d_in[3];
    const float* W2  = (const float*)d_in[4];
    const float* b2  = (const float*)d_in[5];
    const float* W3  = (const float*)d_in[6];
    const float* b3  = (const float*)d_in[7];

    float* out      = (float*)d_out;
    float* out_xyz  = out;                       // (B,S,3)
    float* out_np   = out + (size_t)Bn * Sn * 3; // (B,128,S)

    cudaFuncSetAttribute(sa_kernel, cudaFuncAttributeMaxDynamicSharedMemorySize, SMEM_BYTES);
    sa_kernel<<<NBLK, 512, SMEM_BYTES>>>(xyz, pts, W1, b1, W2, b2, W3, b3,
                                         out_xyz, out_np);
}